// round 1
// baseline (speedup 1.0000x reference)
#include <cuda_runtime.h>
#include <cstdint>

#define BB 2
#define SS 2048
#define DD 1024
#define HH 16
#define HDD 64
// total rows for projections
#define MM (BB * SS)   // 4096

// ---------------------------------------------------------------------------
// Scratch (device globals; allocation is forbidden)
// ---------------------------------------------------------------------------
__device__ float g_q[(size_t)BB * HH * SS * HDD];     // 16 MB  (B,H,S,HD)
__device__ float g_k[(size_t)BB * HH * SS * HDD];     // 16 MB
__device__ float g_v[(size_t)BB * HH * SS * HDD];     // 16 MB
__device__ float g_att[(size_t)BB * SS * DD];         // 16 MB  (B,S,D)
__device__ float g_l[(size_t)BB * HH * SS];           // row sums
__device__ float g_P[(size_t)BB * HH * SS * SS];      // 512 MB fallback for attn_weights

// ---------------------------------------------------------------------------
// GEMM: C[m,n] = sum_k A[m,k] * W[n,k] + bias[n]
// A: (M=4096, K=1024) row-major;  W: (N=1024, K=1024) row-major.
// head_layout: write C as (B,H,S,HD) instead of (M,N).
// Tiles: 128x128, BK=8, 256 threads, 8x8 per thread.
// ---------------------------------------------------------------------------
__global__ __launch_bounds__(256) void gemm_xwt(
    const float* __restrict__ A, const float* __restrict__ W,
    const float* __restrict__ bias, float* __restrict__ C, int head_layout)
{
    __shared__ __align__(16) float As[8][128];
    __shared__ __align__(16) float Bs[8][128];

    const int tid = threadIdx.x;
    const int tx = tid & 15;
    const int ty = tid >> 4;
    const int bx = blockIdx.x;   // N tile
    const int by = blockIdx.y;   // M tile

    float acc[8][8];
#pragma unroll
    for (int i = 0; i < 8; i++)
#pragma unroll
        for (int j = 0; j < 8; j++) acc[i][j] = 0.f;

    const int lr = tid >> 1;          // 0..127
    const int lc = (tid & 1) << 2;    // 0 or 4

    const float* Ag = A + (size_t)(by * 128 + lr) * DD + lc;
    const float* Wg = W + (size_t)(bx * 128 + lr) * DD + lc;

    for (int k0 = 0; k0 < DD; k0 += 8) {
        float4 av = *(const float4*)(Ag + k0);
        float4 wv = *(const float4*)(Wg + k0);
        __syncthreads();
        As[lc + 0][lr] = av.x; As[lc + 1][lr] = av.y;
        As[lc + 2][lr] = av.z; As[lc + 3][lr] = av.w;
        Bs[lc + 0][lr] = wv.x; Bs[lc + 1][lr] = wv.y;
        Bs[lc + 2][lr] = wv.z; Bs[lc + 3][lr] = wv.w;
        __syncthreads();
#pragma unroll
        for (int kk = 0; kk < 8; kk++) {
            float4 a0 = *(const float4*)&As[kk][ty * 8];
            float4 a1 = *(const float4*)&As[kk][ty * 8 + 4];
            float4 b0 = *(const float4*)&Bs[kk][tx * 8];
            float4 b1 = *(const float4*)&Bs[kk][tx * 8 + 4];
            float ar[8] = {a0.x, a0.y, a0.z, a0.w, a1.x, a1.y, a1.z, a1.w};
            float br[8] = {b0.x, b0.y, b0.z, b0.w, b1.x, b1.y, b1.z, b1.w};
#pragma unroll
            for (int i = 0; i < 8; i++)
#pragma unroll
                for (int j = 0; j < 8; j++) acc[i][j] = fmaf(ar[i], br[j], acc[i][j]);
        }
    }

#pragma unroll
    for (int i = 0; i < 8; i++) {
        const int m = by * 128 + ty * 8 + i;
        const int b_ = m >> 11;          // m / SS
        const int s = m & (SS - 1);
#pragma unroll
        for (int j = 0; j < 8; j++) {
            const int n = bx * 128 + tx * 8 + j;
            const float v = acc[i][j] + bias[n];
            if (head_layout) {
                const int h = n >> 6;         // n / HDD
                const int hd = n & (HDD - 1);
                g_setdummy:;
                C[(((size_t)b_ * HH + h) * SS + s) * HDD + hd] = v;
            } else {
                C[(size_t)m * DD + n] = v;
            }
        }
    }
}

// ---------------------------------------------------------------------------
// Scores: for each (bh, 64-row tile): P = exp((Q K^T)/8) on the causal lower
// triangle, 0 elsewhere; accumulate per-row sums into l.
// ---------------------------------------------------------------------------
__global__ __launch_bounds__(256) void scores_kernel(
    const float* __restrict__ q, const float* __restrict__ k,
    float* __restrict__ P, float* __restrict__ l)
{
    __shared__ __align__(16) float Qs[64][64];   // [hd][row]
    __shared__ __align__(16) float Ks[64][64];   // [hd][col]
    __shared__ float red[64][17];

    const int tid = threadIdx.x;
    const int tx = tid & 15;
    const int ty = tid >> 4;
    const int rt = blockIdx.x;   // row tile
    const int bh = blockIdx.y;   // batch*head
    const int r0 = rt * 64;

    const float* qb = q + (size_t)bh * SS * HDD;
    const float* kb = k + (size_t)bh * SS * HDD;
    float* Pb = P + (size_t)bh * SS * SS;

    // load Q tile transposed: Qs[hd][row]
    for (int i = tid; i < 64 * 16; i += 256) {
        const int row = i >> 4;
        const int c4 = (i & 15) << 2;
        float4 v = *(const float4*)(qb + (size_t)(r0 + row) * HDD + c4);
        Qs[c4 + 0][row] = v.x; Qs[c4 + 1][row] = v.y;
        Qs[c4 + 2][row] = v.z; Qs[c4 + 3][row] = v.w;
    }

    float rsum[4] = {0.f, 0.f, 0.f, 0.f};

    for (int jt = 0; jt < SS / 64; jt++) {
        const int j0 = jt * 64;
        if (j0 > r0 + 63) {
            // fully masked tile -> zeros (block-uniform branch; no smem use)
            const float4 z = make_float4(0.f, 0.f, 0.f, 0.f);
#pragma unroll
            for (int i = 0; i < 4; i++) {
                const int row = r0 + ty * 4 + i;
                *(float4*)(Pb + (size_t)row * SS + j0 + tx * 4) = z;
            }
            continue;
        }
        __syncthreads();
        for (int i = tid; i < 64 * 16; i += 256) {
            const int row = i >> 4;
            const int c4 = (i & 15) << 2;
            float4 v = *(const float4*)(kb + (size_t)(j0 + row) * HDD + c4);
            Ks[c4 + 0][row] = v.x; Ks[c4 + 1][row] = v.y;
            Ks[c4 + 2][row] = v.z; Ks[c4 + 3][row] = v.w;
        }
        __syncthreads();

        float acc[4][4];
#pragma unroll
        for (int i = 0; i < 4; i++)
#pragma unroll
            for (int j = 0; j < 4; j++) acc[i][j] = 0.f;

#pragma unroll 16
        for (int kk = 0; kk < 64; kk++) {
            float4 a = *(const float4*)&Qs[kk][ty * 4];
            float4 b = *(const float4*)&Ks[kk][tx * 4];
            float ar[4] = {a.x, a.y, a.z, a.w};
            float br[4] = {b.x, b.y, b.z, b.w};
#pragma unroll
            for (int i = 0; i < 4; i++)
#pragma unroll
                for (int j = 0; j < 4; j++) acc[i][j] = fmaf(ar[i], br[j], acc[i][j]);
        }

#pragma unroll
        for (int i = 0; i < 4; i++) {
            const int row = r0 + ty * 4 + i;
            float pv[4];
#pragma unroll
            for (int j = 0; j < 4; j++) {
                const int col = j0 + tx * 4 + j;
                float p = 0.f;
                if (col <= row) {
                    p = __expf(acc[i][j] * 0.125f);
                    rsum[i] += p;
                }
                pv[j] = p;
            }
            *(float4*)(Pb + (size_t)row * SS + j0 + tx * 4) =
                make_float4(pv[0], pv[1], pv[2], pv[3]);
        }
    }

    __syncthreads();
#pragma unroll
    for (int i = 0; i < 4; i++) red[ty * 4 + i][tx] = rsum[i];
    __syncthreads();
    if (tid < 64) {
        float s = 0.f;
        for (int t = 0; t < 16; t++) s += red[tid][t];
        l[(size_t)bh * SS + r0 + tid] = s;
    }
}

// ---------------------------------------------------------------------------
// Normalize: P[row, 0..r] /= l[row]  (upper triangle already exactly 0)
// ---------------------------------------------------------------------------
__global__ void norm_kernel(float* __restrict__ P, const float* __restrict__ l)
{
    const int row = blockIdx.x;            // 0 .. BB*HH*SS-1
    const int r = row & (SS - 1);
    const float inv = 1.0f / l[row];
    float* Pr = P + (size_t)row * SS;
    for (int c = threadIdx.x; c <= r; c += blockDim.x) Pr[c] *= inv;
}

// ---------------------------------------------------------------------------
// AV: att[b, s, h*64+hd] = sum_j P[bh, s, j] * V[bh, j, hd]   (causal j <= s)
// ---------------------------------------------------------------------------
__global__ __launch_bounds__(256) void av_kernel(
    const float* __restrict__ P, const float* __restrict__ v,
    float* __restrict__ att)
{
    __shared__ __align__(16) float Pt[64][64];   // [j][row]
    __shared__ __align__(16) float Vs[64][64];   // [j][hd]

    const int tid = threadIdx.x;
    const int tx = tid & 15;
    const int ty = tid >> 4;
    const int rt = blockIdx.x;
    const int bh = blockIdx.y;
    const int r0 = rt * 64;

    const float* Pb = P + (size_t)bh * SS * SS;
    const float* vb = v + (size_t)bh * SS * HDD;

    float acc[4][4];
#pragma unroll
    for (int i = 0; i < 4; i++)
#pragma unroll
        for (int j = 0; j < 4; j++) acc[i][j] = 0.f;

    for (int jt = 0; jt <= rt; jt++) {
        const int j0 = jt * 64;
        __syncthreads();
        for (int i = tid; i < 64 * 16; i += 256) {
            const int row = i >> 4;
            const int c4 = (i & 15) << 2;
            float4 pv = *(const float4*)(Pb + (size_t)(r0 + row) * SS + j0 + c4);
            Pt[c4 + 0][row] = pv.x; Pt[c4 + 1][row] = pv.y;
            Pt[c4 + 2][row] = pv.z; Pt[c4 + 3][row] = pv.w;
            float4 vv = *(const float4*)(vb + (size_t)(j0 + row) * HDD + c4);
            *(float4*)&Vs[row][c4] = vv;
        }
        __syncthreads();

#pragma unroll 16
        for (int kk = 0; kk < 64; kk++) {
            float4 a = *(const float4*)&Pt[kk][ty * 4];
            float4 b = *(const float4*)&Vs[kk][tx * 4];
            float ar[4] = {a.x, a.y, a.z, a.w};
            float br[4] = {b.x, b.y, b.z, b.w};
#pragma unroll
            for (int i = 0; i < 4; i++)
#pragma unroll
                for (int j = 0; j < 4; j++) acc[i][j] = fmaf(ar[i], br[j], acc[i][j]);
        }
    }

    const int b_ = bh >> 4;   // bh / HH
    const int h = bh & 15;
#pragma unroll
    for (int i = 0; i < 4; i++) {
        const int s = r0 + ty * 4 + i;
        *(float4*)(att + ((size_t)b_ * SS + s) * DD + h * HDD + tx * 4) =
            make_float4(acc[i][0], acc[i][1], acc[i][2], acc[i][3]);
    }
}

// ---------------------------------------------------------------------------
// Launch
// Inputs (metadata order): query, key, value, mask, Wq, bq, Wk, bk, Wv, bv, Wo, bo
// Output: [output (B,S,D) fp32][attn_weights (B,H,S,S) fp32]  (if out_size holds both)
// ---------------------------------------------------------------------------
extern "C" void kernel_launch(void* const* d_in, const int* in_sizes, int n_in,
                              void* d_out, int out_size)
{
    const float* query = (const float*)d_in[0];
    const float* key_  = (const float*)d_in[1];
    const float* value = (const float*)d_in[2];
    // d_in[3] = mask (bool), implied causal -> unused
    const float* Wq = (const float*)d_in[4];
    const float* bq = (const float*)d_in[5];
    const float* Wk = (const float*)d_in[6];
    const float* bk = (const float*)d_in[7];
    const float* Wv = (const float*)d_in[8];
    const float* bv = (const float*)d_in[9];
    const float* Wo = (const float*)d_in[10];
    const float* bo = (const float*)d_in[11];
    float* out = (float*)d_out;

    float *q_, *k_, *v_, *att_, *l_, *Pfb_;
    cudaGetSymbolAddress((void**)&q_,   g_q);
    cudaGetSymbolAddress((void**)&k_,   g_k);
    cudaGetSymbolAddress((void**)&v_,   g_v);
    cudaGetSymbolAddress((void**)&att_, g_att);
    cudaGetSymbolAddress((void**)&l_,   g_l);
    cudaGetSymbolAddress((void**)&Pfb_, g_P);

    const size_t OUT0 = (size_t)BB * SS * DD;            // 4,194,304
    const size_t PE   = (size_t)BB * HH * SS * SS;       // 134,217,728
    float* P = ((size_t)out_size >= OUT0 + PE) ? (out + OUT0) : Pfb_;

    dim3 gproj(DD / 128, MM / 128);          // (8, 32)
    gemm_xwt<<<gproj, 256>>>(query, Wq, bq, q_, 1);
    gemm_xwt<<<gproj, 256>>>(key_,  Wk, bk, k_, 1);
    gemm_xwt<<<gproj, 256>>>(value, Wv, bv, v_, 1);

    dim3 gatt(SS / 64, BB * HH);             // (32, 32)
    scores_kernel<<<gatt, 256>>>(q_, k_, P, l_);
    norm_kernel<<<BB * HH * SS, 256>>>(P, l_);
    av_kernel<<<gatt, 256>>>(P, v_, att_);

    gemm_xwt<<<gproj, 256>>>(att_, Wo, bo, out, 0);
}

// round 4
// speedup vs baseline: 1.1771x; 1.1771x over previous
#include <cuda_runtime.h>
#include <cstdint>

#define BB 2
#define SS 2048
#define DD 1024
#define HH 16
#define HDD 64
#define MM (BB * SS)   // 4096

// ---------------------------------------------------------------------------
// Scratch (device globals; allocation is forbidden)
// ---------------------------------------------------------------------------
__device__ float g_q[(size_t)BB * HH * SS * HDD];     // 16 MB  (B,H,S,HD)
__device__ float g_k[(size_t)BB * HH * SS * HDD];     // 16 MB
__device__ float g_v[(size_t)BB * HH * SS * HDD];     // 16 MB
__device__ float g_att[(size_t)BB * SS * DD];         // 16 MB  (B,S,D)
__device__ float g_P[(size_t)BB * HH * SS * SS];      // 512 MB fallback for attn_weights

// ---------------------------------------------------------------------------
// GEMM: C[m,n] = sum_k A[m,k] * W[n,k] + bias[n]
// A: (M=4096, K=1024) row-major;  W: (N=1024, K=1024) row-major.
// head_layout: write C as (B,H,S,HD) instead of (M,N).
// 128x128 tile, BK=8, 256 threads, 8x8 per thread, 2-stage smem pipeline.
// ---------------------------------------------------------------------------
__global__ __launch_bounds__(256) void gemm_xwt(
    const float* __restrict__ A, const float* __restrict__ W,
    const float* __restrict__ bias, float* __restrict__ C, int head_layout)
{
    __shared__ __align__(16) float As[2][8][128];
    __shared__ __align__(16) float Bs[2][8][128];

    const int tid = threadIdx.x;
    const int tx = tid & 15;
    const int ty = tid >> 4;
    const int bx = blockIdx.x;   // N tile
    const int by = blockIdx.y;   // M tile

    float acc[8][8];
#pragma unroll
    for (int i = 0; i < 8; i++)
#pragma unroll
        for (int j = 0; j < 8; j++) acc[i][j] = 0.f;

    // hoist bias for this thread's 8 output columns
    float bs[8];
    {
        float4 b0 = *(const float4*)(bias + bx * 128 + tx * 8);
        float4 b1 = *(const float4*)(bias + bx * 128 + tx * 8 + 4);
        bs[0] = b0.x; bs[1] = b0.y; bs[2] = b0.z; bs[3] = b0.w;
        bs[4] = b1.x; bs[5] = b1.y; bs[6] = b1.z; bs[7] = b1.w;
    }

    const int lr = tid >> 1;          // 0..127
    const int lc = (tid & 1) << 2;    // 0 or 4

    const float* Ag = A + (size_t)(by * 128 + lr) * DD + lc;
    const float* Wg = W + (size_t)(bx * 128 + lr) * DD + lc;

    // prologue: stage 0
    {
        float4 av = *(const float4*)(Ag);
        float4 wv = *(const float4*)(Wg);
        As[0][lc + 0][lr] = av.x; As[0][lc + 1][lr] = av.y;
        As[0][lc + 2][lr] = av.z; As[0][lc + 3][lr] = av.w;
        Bs[0][lc + 0][lr] = wv.x; Bs[0][lc + 1][lr] = wv.y;
        Bs[0][lc + 2][lr] = wv.z; Bs[0][lc + 3][lr] = wv.w;
    }
    __syncthreads();

    int cur = 0;
    for (int k0 = 8; k0 <= DD; k0 += 8) {
        const bool has = (k0 < DD);
        float4 av, wv;
        if (has) {
            av = *(const float4*)(Ag + k0);
            wv = *(const float4*)(Wg + k0);
        }
#pragma unroll
        for (int kk = 0; kk < 8; kk++) {
            float4 a0 = *(const float4*)&As[cur][kk][ty * 8];
            float4 a1 = *(const float4*)&As[cur][kk][ty * 8 + 4];
            float4 b0 = *(const float4*)&Bs[cur][kk][tx * 8];
            float4 b1 = *(const float4*)&Bs[cur][kk][tx * 8 + 4];
            float ar[8] = {a0.x, a0.y, a0.z, a0.w, a1.x, a1.y, a1.z, a1.w};
            float br[8] = {b0.x, b0.y, b0.z, b0.w, b1.x, b1.y, b1.z, b1.w};
#pragma unroll
            for (int i = 0; i < 8; i++)
#pragma unroll
                for (int j = 0; j < 8; j++) acc[i][j] = fmaf(ar[i], br[j], acc[i][j]);
        }
        if (has) {
            const int nxt = cur ^ 1;
            As[nxt][lc + 0][lr] = av.x; As[nxt][lc + 1][lr] = av.y;
            As[nxt][lc + 2][lr] = av.z; As[nxt][lc + 3][lr] = av.w;
            Bs[nxt][lc + 0][lr] = wv.x; Bs[nxt][lc + 1][lr] = wv.y;
            Bs[nxt][lc + 2][lr] = wv.z; Bs[nxt][lc + 3][lr] = wv.w;
            __syncthreads();
            cur = nxt;
        }
    }

#pragma unroll
    for (int i = 0; i < 8; i++) {
        const int m = by * 128 + ty * 8 + i;
        const int b_ = m >> 11;          // m / SS
        const int s = m & (SS - 1);
#pragma unroll
        for (int j = 0; j < 8; j++) {
            const int n = bx * 128 + tx * 8 + j;
            const float v = acc[i][j] + bs[j];
            if (head_layout) {
                const int h = n >> 6;
                const int hd = n & (HDD - 1);
                C[(((size_t)b_ * HH + h) * SS + s) * HDD + hd] = v;
            } else {
                C[(size_t)m * DD + n] = v;
            }
        }
    }
}

// ---------------------------------------------------------------------------
// Fused attention: per (bh, 64-row tile)
//   phase 1: loop over K/V tiles j<=rt:
//            S = QK^T/8 -> p=exp(S) (causal), rowsum += p,
//            write unnormalized p to P, O += p @ V   (registers)
//   phase 2: O /= rowsum -> att; rescale own P elements; zero-fill j>rt.
// ---------------------------------------------------------------------------
__global__ __launch_bounds__(256) void attn_fused(
    const float* __restrict__ q, const float* __restrict__ k,
    const float* __restrict__ v, float* __restrict__ P,
    float* __restrict__ att)
{
    __shared__ __align__(16) float Qs[64][64];   // [hd][row]
    __shared__ __align__(16) float KV[64][64];   // K: [hd][col], then V: [j][d]
    __shared__ __align__(16) float Ps[64][64];   // [row][col]

    const int tid = threadIdx.x;
    const int tx = tid & 15;
    const int ty = tid >> 4;
    const int rt = (int)gridDim.x - 1 - (int)blockIdx.x;  // big tiles first
    const int bh = blockIdx.y;
    const int r0 = rt * 64;

    const float* qb = q + (size_t)bh * SS * HDD;
    const float* kb = k + (size_t)bh * SS * HDD;
    const float* vb = v + (size_t)bh * SS * HDD;
    float* Pb = P + (size_t)bh * SS * SS;

    // load Q tile transposed: Qs[hd][row]
    for (int i = tid; i < 64 * 16; i += 256) {
        const int row = i >> 4;
        const int c4 = (i & 15) << 2;
        float4 t = *(const float4*)(qb + (size_t)(r0 + row) * HDD + c4);
        Qs[c4 + 0][row] = t.x; Qs[c4 + 1][row] = t.y;
        Qs[c4 + 2][row] = t.z; Qs[c4 + 3][row] = t.w;
    }

    float o[4][4];
#pragma unroll
    for (int i = 0; i < 4; i++)
#pragma unroll
        for (int j = 0; j < 4; j++) o[i][j] = 0.f;
    float rsum[4] = {0.f, 0.f, 0.f, 0.f};

    for (int jt = 0; jt <= rt; jt++) {
        const int j0 = jt * 64;
        __syncthreads();  // protect Qs (first iter), KV/Ps from previous iter
        // load K tile transposed: KV[hd][col]
        for (int i = tid; i < 64 * 16; i += 256) {
            const int row = i >> 4;
            const int c4 = (i & 15) << 2;
            float4 t = *(const float4*)(kb + (size_t)(j0 + row) * HDD + c4);
            KV[c4 + 0][row] = t.x; KV[c4 + 1][row] = t.y;
            KV[c4 + 2][row] = t.z; KV[c4 + 3][row] = t.w;
        }
        __syncthreads();

        float s[4][4];
#pragma unroll
        for (int i = 0; i < 4; i++)
#pragma unroll
            for (int j = 0; j < 4; j++) s[i][j] = 0.f;

#pragma unroll 16
        for (int kk = 0; kk < 64; kk++) {
            float4 a = *(const float4*)&Qs[kk][ty * 4];
            float4 b = *(const float4*)&KV[kk][tx * 4];
            float ar[4] = {a.x, a.y, a.z, a.w};
            float br[4] = {b.x, b.y, b.z, b.w};
#pragma unroll
            for (int i = 0; i < 4; i++)
#pragma unroll
                for (int j = 0; j < 4; j++) s[i][j] = fmaf(ar[i], br[j], s[i][j]);
        }

        // exp + causal mask; write unnorm P; stash tile in Ps for AV
#pragma unroll
        for (int i = 0; i < 4; i++) {
            const int row = r0 + ty * 4 + i;
            float pv[4];
#pragma unroll
            for (int j = 0; j < 4; j++) {
                const int col = j0 + tx * 4 + j;
                float p = 0.f;
                if (col <= row) {
                    p = __expf(s[i][j] * 0.125f);
                    rsum[i] += p;
                }
                pv[j] = p;
            }
            float4 pq = make_float4(pv[0], pv[1], pv[2], pv[3]);
            *(float4*)(Pb + (size_t)row * SS + j0 + tx * 4) = pq;
            *(float4*)&Ps[ty * 4 + i][tx * 4] = pq;
        }
        __syncthreads();  // Ps complete; KV (K) reads done

        // load V tile natural: KV[j][d]
        for (int i = tid; i < 64 * 16; i += 256) {
            const int row = i >> 4;
            const int c4 = (i & 15) << 2;
            *(float4*)&KV[row][c4] =
                *(const float4*)(vb + (size_t)(j0 + row) * HDD + c4);
        }
        __syncthreads();

        // O += Ps @ V
#pragma unroll 16
        for (int kk = 0; kk < 64; kk++) {
            float4 b = *(const float4*)&KV[kk][tx * 4];
            float br[4] = {b.x, b.y, b.z, b.w};
#pragma unroll
            for (int i = 0; i < 4; i++) {
                const float a = Ps[ty * 4 + i][kk];
#pragma unroll
                for (int j = 0; j < 4; j++) o[i][j] = fmaf(a, br[j], o[i][j]);
            }
        }
    }

    // row sums: butterfly across tx (lane bits 0..3)
    float inv[4];
#pragma unroll
    for (int i = 0; i < 4; i++) {
#pragma unroll
        for (int off = 1; off < 16; off <<= 1)
            rsum[i] += __shfl_xor_sync(0xffffffff, rsum[i], off);
        inv[i] = 1.0f / rsum[i];
    }

    // write O (normalized) to att (B,S,D)
    const int b_ = bh >> 4;
    const int h = bh & 15;
#pragma unroll
    for (int i = 0; i < 4; i++) {
        const int srow = r0 + ty * 4 + i;
        *(float4*)(att + ((size_t)b_ * SS + srow) * DD + h * HDD + tx * 4) =
            make_float4(o[i][0] * inv[i], o[i][1] * inv[i],
                        o[i][2] * inv[i], o[i][3] * inv[i]);
    }

    // phase 2: rescale exactly the P elements this thread wrote (per-thread RAW)
    for (int jt = 0; jt <= rt; jt++) {
#pragma unroll
        for (int i = 0; i < 4; i++) {
            float4* p = (float4*)(Pb + (size_t)(r0 + ty * 4 + i) * SS + jt * 64 + tx * 4);
            float4 t = *p;
            t.x *= inv[i]; t.y *= inv[i]; t.z *= inv[i]; t.w *= inv[i];
            *p = t;
        }
    }
    // zero-fill fully masked tiles (j > r)
    const float4 z = make_float4(0.f, 0.f, 0.f, 0.f);
    for (int jt = rt + 1; jt < SS / 64; jt++) {
#pragma unroll
        for (int i = 0; i < 4; i++)
            *(float4*)(Pb + (size_t)(r0 + ty * 4 + i) * SS + jt * 64 + tx * 4) = z;
    }
}

// ---------------------------------------------------------------------------
// Launch
// Inputs: query, key, value, mask, Wq, bq, Wk, bk, Wv, bv, Wo, bo
// Output: [output (B,S,D) fp32][attn_weights (B,H,S,S) fp32]
// ---------------------------------------------------------------------------
extern "C" void kernel_launch(void* const* d_in, const int* in_sizes, int n_in,
                              void* d_out, int out_size)
{
    const float* query = (const float*)d_in[0];
    const float* key_  = (const float*)d_in[1];
    const float* value = (const float*)d_in[2];
    // d_in[3] = mask (bool): causal, implied -> unused
    const float* Wq = (const float*)d_in[4];
    const float* bq = (const float*)d_in[5];
    const float* Wk = (const float*)d_in[6];
    const float* bk = (const float*)d_in[7];
    const float* Wv = (const float*)d_in[8];
    const float* bv = (const float*)d_in[9];
    const float* Wo = (const float*)d_in[10];
    const float* bo = (const float*)d_in[11];
    float* out = (float*)d_out;

    float *q_, *k_, *v_, *att_, *Pfb_;
    cudaGetSymbolAddress((void**)&q_,   g_q);
    cudaGetSymbolAddress((void**)&k_,   g_k);
    cudaGetSymbolAddress((void**)&v_,   g_v);
    cudaGetSymbolAddress((void**)&att_, g_att);
    cudaGetSymbolAddress((void**)&Pfb_, g_P);

    const size_t OUT0 = (size_t)BB * SS * DD;            // 4,194,304
    const size_t PE   = (size_t)BB * HH * SS * SS;       // 134,217,728
    float* P = ((size_t)out_size >= OUT0 + PE) ? (out + OUT0) : Pfb_;

    dim3 gproj(DD / 128, MM / 128);          // (8, 32)
    gemm_xwt<<<gproj, 256>>>(query, Wq, bq, q_, 1);
    gemm_xwt<<<gproj, 256>>>(key_,  Wk, bk, k_, 1);
    gemm_xwt<<<gproj, 256>>>(value, Wv, bv, v_, 1);

    dim3 gatt(SS / 64, BB * HH);             // (32, 32)
    attn_fused<<<gatt, 256>>>(q_, k_, v_, P, att_);

    gemm_xwt<<<gproj, 256>>>(att_, Wo, bo, out, 0);
}

// round 11
// speedup vs baseline: 1.7129x; 1.4553x over previous
#include <cuda_runtime.h>
#include <cuda_bf16.h>
#include <cstdint>

#define BB 2
#define SS 2048
#define DD 1024
#define HH 16
#define HDD 64
#define MM (BB * SS)   // 4096

// ---------------------------------------------------------------------------
// Arch-specific gate: tcgen05 exists only on sm_10xa targets. The harness
// also compiles a generic compute_103 PTX pass, which must see a stub.
// ---------------------------------------------------------------------------
#if defined(__CUDA_ARCH__) && (__CUDA_ARCH__ >= 1000)
#  if defined(__CUDA_ARCH_HAS_FEATURE__)
#    if __CUDA_ARCH_HAS_FEATURE__(SM103_ALL) || __CUDA_ARCH_HAS_FEATURE__(SM100_ALL) || __CUDA_ARCH_HAS_FEATURE__(SM101_ALL)
#      define HAS_TCGEN05 1
#    endif
#  endif
#  if !defined(HAS_TCGEN05) && defined(__CUDA_ARCH_SPECIFIC__)
#    define HAS_TCGEN05 1
#  endif
#  if !defined(HAS_TCGEN05) && defined(__CUDA_ARCH_FEAT_SM103_ALL)
#    define HAS_TCGEN05 1
#  endif
#  if !defined(HAS_TCGEN05) && defined(__CUDA_ARCH_FEAT_SM100_ALL)
#    define HAS_TCGEN05 1
#  endif
#endif

// ---------------------------------------------------------------------------
// Scratch (device globals; allocation is forbidden)
// ---------------------------------------------------------------------------
__device__ float g_q[(size_t)BB * HH * SS * HDD];     // 16 MB  (B,H,S,HD)
__device__ float g_k[(size_t)BB * HH * SS * HDD];     // 16 MB
__device__ float g_v[(size_t)BB * HH * SS * HDD];     // 16 MB
__device__ float g_att[(size_t)BB * SS * DD];         // 16 MB  (B,S,D)
__device__ float g_P[(size_t)BB * HH * SS * SS];      // 512 MB fallback for attn_weights
__device__ __nv_bfloat16 g_ah[(size_t)MM * DD];       // 8 MB  activation hi
__device__ __nv_bfloat16 g_al[(size_t)MM * DD];       // 8 MB  activation lo
__device__ __nv_bfloat16 g_wh[(size_t)DD * DD];       // 2 MB  weight hi
__device__ __nv_bfloat16 g_wl[(size_t)DD * DD];       // 2 MB  weight lo

#ifdef HAS_TCGEN05
// ---------------------------------------------------------------------------
// PTX helpers (tcgen05 / mbarrier) — arch-specific pass only
// ---------------------------------------------------------------------------
__device__ __forceinline__ uint32_t smem_u32(const void* p) {
    uint32_t a;
    asm("{ .reg .u64 t; cvta.to.shared.u64 t, %1; cvt.u32.u64 %0, t; }"
        : "=r"(a) : "l"(p));
    return a;
}
__device__ __forceinline__ uint32_t elect1() {
    uint32_t pred;
    asm volatile(
        "{ .reg .pred p; elect.sync _|p, 0xFFFFFFFF; selp.b32 %0, 1, 0, p; }"
        : "=r"(pred));
    return pred;
}

#define TC_ALLOC(smem_addr, ncols) \
    asm volatile("tcgen05.alloc.cta_group::1.sync.aligned.shared::cta.b32 [%0], %1;" \
                 :: "r"(smem_addr), "r"((uint32_t)(ncols)) : "memory")
#define TC_RELINQ() \
    asm volatile("tcgen05.relinquish_alloc_permit.cta_group::1.sync.aligned;")
#define TC_DEALLOC(tmem, ncols) \
    asm volatile("tcgen05.dealloc.cta_group::1.sync.aligned.b32 %0, %1;" \
                 :: "r"(tmem), "r"((uint32_t)(ncols)))
#define TC_COMMIT(mbar) \
    asm volatile("tcgen05.commit.cta_group::1.mbarrier::arrive::one.shared::cluster.b64 [%0];" \
                 :: "r"(mbar) : "memory")
#define TC_FENCE_AFTER() \
    asm volatile("tcgen05.fence::after_thread_sync;" ::: "memory")
#define TC_WAIT_LD() \
    asm volatile("tcgen05.wait::ld.sync.aligned;" ::: "memory")
#define FENCE_ASYNC_SHARED() \
    asm volatile("fence.proxy.async.shared::cta;" ::: "memory")
#define MBAR_INIT(mbar, cnt) \
    asm volatile("mbarrier.init.shared.b64 [%0], %1;" \
                 :: "r"(mbar), "r"((uint32_t)(cnt)) : "memory")
#define MBAR_INVAL(mbar) \
    asm volatile("mbarrier.inval.shared.b64 [%0];" :: "r"(mbar) : "memory")

#define MBAR_WAIT_PARITY(mbar_a, par) do {                                      \
    uint32_t _m = (mbar_a); uint32_t _p = (par); uint32_t _d;                   \
    asm volatile(                                                               \
        "{\n\t.reg .pred p;\n\t"                                                \
        "mbarrier.try_wait.parity.acquire.cta.shared::cta.b64 p, [%1], %2;\n\t" \
        "selp.b32 %0, 1, 0, p;\n\t}"                                            \
        : "=r"(_d) : "r"(_m), "r"(_p) : "memory");                              \
    if (!_d) {                                                                  \
        asm volatile(                                                           \
            "{\n\t.reg .pred P1;\n\t"                                           \
            "WL_%=:\n\t"                                                        \
            "mbarrier.try_wait.parity.acquire.cta.shared::cta.b64 P1, [%0], %1, 0x989680;\n\t" \
            "@P1 bra.uni WD_%=;\n\t"                                            \
            "bra.uni WL_%=;\n\t"                                                \
            "WD_%=:\n\t}"                                                       \
            :: "r"(_m), "r"(_p) : "memory");                                    \
    }                                                                           \
} while (0)

#define TC_LD_32X32B_X32(r, tmem_addr) \
    asm volatile( \
        "tcgen05.ld.sync.aligned.32x32b.x32.b32 " \
        "{%0, %1, %2, %3, %4, %5, %6, %7, " \
        " %8, %9, %10, %11, %12, %13, %14, %15, " \
        " %16, %17, %18, %19, %20, %21, %22, %23, " \
        " %24, %25, %26, %27, %28, %29, %30, %31}, [%32];" \
        : "=r"((r)[0]),  "=r"((r)[1]),  "=r"((r)[2]),  "=r"((r)[3]), \
          "=r"((r)[4]),  "=r"((r)[5]),  "=r"((r)[6]),  "=r"((r)[7]), \
          "=r"((r)[8]),  "=r"((r)[9]),  "=r"((r)[10]), "=r"((r)[11]), \
          "=r"((r)[12]), "=r"((r)[13]), "=r"((r)[14]), "=r"((r)[15]), \
          "=r"((r)[16]), "=r"((r)[17]), "=r"((r)[18]), "=r"((r)[19]), \
          "=r"((r)[20]), "=r"((r)[21]), "=r"((r)[22]), "=r"((r)[23]), \
          "=r"((r)[24]), "=r"((r)[25]), "=r"((r)[26]), "=r"((r)[27]), \
          "=r"((r)[28]), "=r"((r)[29]), "=r"((r)[30]), "=r"((r)[31]) \
        : "r"(tmem_addr))

// SS-mode cg1 bf16 MMA: D[m,n] += A[m,k]*B[n,k], A/B K-major in smem.
__device__ __forceinline__ void mma_bf16_ss(
    uint32_t d, uint64_t da, uint64_t db, uint32_t idesc, uint32_t en)
{
    asm volatile(
        "{\n\t"
        ".reg .pred p;\n\t"
        "setp.ne.u32 p, %5, 0;\n\t"
        "tcgen05.mma.cta_group::1.kind::f16 [%0], %1, %2, %3, {%4, %4, %4, %4}, p;\n\t"
        "}"
        :: "r"(d), "l"(da), "l"(db), "r"(idesc), "r"(0u), "r"(en)
        : "memory");
}

// SW128 smem descriptor: layout=2(SW128), version=1, SBO=64, LBO=1
static __device__ __forceinline__ uint64_t make_desc(uint32_t addr) {
    const uint64_t base =
        (uint64_t(2) << 61) | (uint64_t(1) << 46) |
        (uint64_t(64) << 32) | (uint64_t(1) << 16);
    return base | ((uint64_t)(addr >> 4) & 0x3FFF);
}

// idesc: f32 acc, bf16 a/b, M=128, N=128
#define GT_IDESC ((1u << 4) | (1u << 7) | (1u << 10) | ((128u / 8) << 17) | ((128u / 16) << 24))
#endif  // HAS_TCGEN05

// ---------------------------------------------------------------------------
// split: x(fp32) -> hi, lo (bf16), x ≈ hi + lo
// ---------------------------------------------------------------------------
__global__ __launch_bounds__(256) void split_kernel(
    const float* __restrict__ x, __nv_bfloat16* __restrict__ hi,
    __nv_bfloat16* __restrict__ lo, int n)
{
    const int stride = gridDim.x * blockDim.x * 4;
    for (int i = (blockIdx.x * blockDim.x + threadIdx.x) * 4; i < n; i += stride) {
        float4 v = *(const float4*)(x + i);
        __nv_bfloat16 h0 = __float2bfloat16(v.x);
        __nv_bfloat16 h1 = __float2bfloat16(v.y);
        __nv_bfloat16 h2 = __float2bfloat16(v.z);
        __nv_bfloat16 h3 = __float2bfloat16(v.w);
        __nv_bfloat162 hp0; hp0.x = h0; hp0.y = h1;
        __nv_bfloat162 hp1; hp1.x = h2; hp1.y = h3;
        *(__nv_bfloat162*)(hi + i)     = hp0;
        *(__nv_bfloat162*)(hi + i + 2) = hp1;
        __nv_bfloat162 lp0, lp1;
        lp0.x = __float2bfloat16(v.x - __bfloat162float(h0));
        lp0.y = __float2bfloat16(v.y - __bfloat162float(h1));
        lp1.x = __float2bfloat16(v.z - __bfloat162float(h2));
        lp1.y = __float2bfloat16(v.w - __bfloat162float(h3));
        *(__nv_bfloat162*)(lo + i)     = lp0;
        *(__nv_bfloat162*)(lo + i + 2) = lp1;
    }
}

// ---------------------------------------------------------------------------
// Tensor-core GEMM: C[m,n] = sum_k A[m,k]*W[n,k] + bias[n]
// A,W given as bf16 (hi,lo) pairs; computes Ah*Wh + Ah*Wl + Al*Wh in fp32 TMEM.
// 128x128 tile/CTA, K chunks of 64, double-buffered smem, 256 threads.
// Pipeline sync: ONE MBARRIER PER STAGE (2 total) — single-barrier parity
// reuse aliases at distance 2 and deadlocks (observed R8 hang).
// ---------------------------------------------------------------------------
#define KCH 64
#define NCHUNK (DD / KCH)          // 16
#define TILE_B 16384               // one 128x64 bf16 tile
#define STAGE_B (4 * TILE_B)       // Ah, Al, Bh, Bl
#define GT_SMEM (1024 + 2 * STAGE_B)  // 132096

__global__ __launch_bounds__(256) void gemm_tc(
    const __nv_bfloat16* __restrict__ ah, const __nv_bfloat16* __restrict__ al,
    const __nv_bfloat16* __restrict__ wh, const __nv_bfloat16* __restrict__ wl,
    const float* __restrict__ bias, float* __restrict__ C, int head_layout)
{
#ifdef HAS_TCGEN05
    extern __shared__ __align__(1024) char smem[];
    const uint32_t sb = smem_u32(smem);
    const int tid = threadIdx.x;
    const int wid = tid >> 5;
    const int lid = tid & 31;
    const int bx = blockIdx.x;   // N tile (0..7)
    const int by = blockIdx.y;   // M tile (0..31)

    // TMEM alloc (warp 0), per-stage mbar init
    if (wid == 0) TC_ALLOC(sb, 128);
    __syncthreads();
    uint32_t tmem;
    asm volatile("ld.shared.b32 %0, [%1];" : "=r"(tmem) : "r"(sb));
    if (tid == 0) { MBAR_INIT(sb + 8, 1); MBAR_INIT(sb + 16, 1); }
    if (wid == 0) TC_RELINQ();
    __syncthreads();

    // load mapping: thread t -> row t>>1; lane-pair interleave so each pair
    // covers consecutive 32B of a 128B row. byte in row = (t&1)*16 + 32*i
    const int row = tid >> 1;
    const int cb0 = (tid & 1) * 8;          // bf16 col base
    const __nv_bfloat16* pAh = ah + (size_t)(by * 128 + row) * DD + cb0;
    const __nv_bfloat16* pAl = al + (size_t)(by * 128 + row) * DD + cb0;
    const __nv_bfloat16* pBh = wh + (size_t)(bx * 128 + row) * DD + cb0;
    const __nv_bfloat16* pBl = wl + (size_t)(bx * 128 + row) * DD + cb0;
    const uint32_t bo = (uint32_t)(row * 128 + (tid & 1) * 16);

    for (int c = 0; c < NCHUNK; c++) {
        const int kc = c * KCH;
        const int stg = c & 1;
        uint4 va_h[4], va_l[4], vb_h[4], vb_l[4];
#pragma unroll
        for (int i = 0; i < 4; i++) {
            va_h[i] = *(const uint4*)(pAh + kc + 16 * i);
            va_l[i] = *(const uint4*)(pAl + kc + 16 * i);
            vb_h[i] = *(const uint4*)(pBh + kc + 16 * i);
            vb_l[i] = *(const uint4*)(pBl + kc + 16 * i);
        }
        if (c >= 2) {
            // wait for MMA batch that consumed this stage at chunk c-2:
            // stage-phase index (c>>1)-1
            const uint32_t ph = (uint32_t)((c >> 1) - 1);
            MBAR_WAIT_PARITY(sb + 8 + 8 * stg, ph & 1);
        }
        char* st = smem + 1024 + stg * STAGE_B;
#pragma unroll
        for (int i = 0; i < 4; i++) {
            uint32_t off = bo + 32 * i;
            uint32_t sw = off ^ ((off >> 3) & 0x70);
            *(uint4*)(st + sw)               = va_h[i];
            *(uint4*)(st + TILE_B + sw)      = va_l[i];
            *(uint4*)(st + 2 * TILE_B + sw)  = vb_h[i];
            *(uint4*)(st + 3 * TILE_B + sw)  = vb_l[i];
        }
        FENCE_ASYNC_SHARED();   // order generic smem writes before async-proxy MMA reads
        __syncthreads();
        if (wid == 0 && elect1()) {
            const uint32_t sa = sb + 1024 + stg * STAGE_B;
            const uint64_t dAh = make_desc(sa);
            const uint64_t dAl = make_desc(sa + TILE_B);
            const uint64_t dBh = make_desc(sa + 2 * TILE_B);
            const uint64_t dBl = make_desc(sa + 3 * TILE_B);
#pragma unroll
            for (int k = 0; k < 4; k++) {
                mma_bf16_ss(tmem, dAh + k * 2, dBh + k * 2, GT_IDESC,
                            (c == 0 && k == 0) ? 0u : 1u);
                mma_bf16_ss(tmem, dAh + k * 2, dBl + k * 2, GT_IDESC, 1u);
                mma_bf16_ss(tmem, dAl + k * 2, dBh + k * 2, GT_IDESC, 1u);
            }
            TC_COMMIT(sb + 8 + 8 * stg);
        }
    }
    // tail: last stage-phase of each barrier is (NCHUNK/2 - 1) = 7 (parity 1)
    MBAR_WAIT_PARITY(sb + 8,  (uint32_t)((NCHUNK / 2 - 1) & 1));
    MBAR_WAIT_PARITY(sb + 16, (uint32_t)((NCHUNK / 2 - 1) & 1));
    TC_FENCE_AFTER();

    // epilogue: warps 0..3 read D (their subpartitions), add bias, store
    if (wid < 4) {
        const int m = by * 128 + wid * 32 + lid;
        const int b_ = m >> 11;
        const int s = m & (SS - 1);
#pragma unroll
        for (int cb = 0; cb < 4; cb++) {
            uint32_t r[32];
            TC_LD_32X32B_X32(r, tmem + cb * 32);
            TC_WAIT_LD();
#pragma unroll
            for (int j = 0; j < 32; j++) {
                const int n = bx * 128 + cb * 32 + j;
                const float v = __uint_as_float(r[j]) + bias[n];
                if (head_layout) {
                    const int h = n >> 6;
                    const int hd = n & (HDD - 1);
                    C[(((size_t)b_ * HH + h) * SS + s) * HDD + hd] = v;
                } else {
                    C[(size_t)m * DD + n] = v;
                }
            }
        }
    }
    __syncthreads();
    if (tid == 0) { MBAR_INVAL(sb + 8); MBAR_INVAL(sb + 16); }
    __syncthreads();
    if (wid == 0) TC_DEALLOC(tmem, 128);
#endif  // HAS_TCGEN05
}

// ---------------------------------------------------------------------------
// Fused attention (unchanged from passing R4 kernel)
// ---------------------------------------------------------------------------
__global__ __launch_bounds__(256) void attn_fused(
    const float* __restrict__ q, const float* __restrict__ k,
    const float* __restrict__ v, float* __restrict__ P,
    float* __restrict__ att)
{
    __shared__ __align__(16) float Qs[64][64];   // [hd][row]
    __shared__ __align__(16) float KV[64][64];   // K: [hd][col], then V: [j][d]
    __shared__ __align__(16) float Ps[64][64];   // [row][col]

    const int tid = threadIdx.x;
    const int tx = tid & 15;
    const int ty = tid >> 4;
    const int rt = (int)gridDim.x - 1 - (int)blockIdx.x;  // big tiles first
    const int bh = blockIdx.y;
    const int r0 = rt * 64;

    const float* qb = q + (size_t)bh * SS * HDD;
    const float* kb = k + (size_t)bh * SS * HDD;
    const float* vb = v + (size_t)bh * SS * HDD;
    float* Pb = P + (size_t)bh * SS * SS;

    for (int i = tid; i < 64 * 16; i += 256) {
        const int row = i >> 4;
        const int c4 = (i & 15) << 2;
        float4 t = *(const float4*)(qb + (size_t)(r0 + row) * HDD + c4);
        Qs[c4 + 0][row] = t.x; Qs[c4 + 1][row] = t.y;
        Qs[c4 + 2][row] = t.z; Qs[c4 + 3][row] = t.w;
    }

    float o[4][4];
#pragma unroll
    for (int i = 0; i < 4; i++)
#pragma unroll
        for (int j = 0; j < 4; j++) o[i][j] = 0.f;
    float rsum[4] = {0.f, 0.f, 0.f, 0.f};

    for (int jt = 0; jt <= rt; jt++) {
        const int j0 = jt * 64;
        __syncthreads();
        for (int i = tid; i < 64 * 16; i += 256) {
            const int row = i >> 4;
            const int c4 = (i & 15) << 2;
            float4 t = *(const float4*)(kb + (size_t)(j0 + row) * HDD + c4);
            KV[c4 + 0][row] = t.x; KV[c4 + 1][row] = t.y;
            KV[c4 + 2][row] = t.z; KV[c4 + 3][row] = t.w;
        }
        __syncthreads();

        float s[4][4];
#pragma unroll
        for (int i = 0; i < 4; i++)
#pragma unroll
            for (int j = 0; j < 4; j++) s[i][j] = 0.f;

#pragma unroll 16
        for (int kk = 0; kk < 64; kk++) {
            float4 a = *(const float4*)&Qs[kk][ty * 4];
            float4 b = *(const float4*)&KV[kk][tx * 4];
            float ar[4] = {a.x, a.y, a.z, a.w};
            float br[4] = {b.x, b.y, b.z, b.w};
#pragma unroll
            for (int i = 0; i < 4; i++)
#pragma unroll
                for (int j = 0; j < 4; j++) s[i][j] = fmaf(ar[i], br[j], s[i][j]);
        }

#pragma unroll
        for (int i = 0; i < 4; i++) {
            const int row = r0 + ty * 4 + i;
            float pv[4];
#pragma unroll
            for (int j = 0; j < 4; j++) {
                const int col = j0 + tx * 4 + j;
                float p = 0.f;
                if (col <= row) {
                    p = __expf(s[i][j] * 0.125f);
                    rsum[i] += p;
                }
                pv[j] = p;
            }
            float4 pq = make_float4(pv[0], pv[1], pv[2], pv[3]);
            *(float4*)(Pb + (size_t)row * SS + j0 + tx * 4) = pq;
            *(float4*)&Ps[ty * 4 + i][tx * 4] = pq;
        }
        __syncthreads();

        for (int i = tid; i < 64 * 16; i += 256) {
            const int row = i >> 4;
            const int c4 = (i & 15) << 2;
            *(float4*)&KV[row][c4] =
                *(const float4*)(vb + (size_t)(j0 + row) * HDD + c4);
        }
        __syncthreads();

#pragma unroll 16
        for (int kk = 0; kk < 64; kk++) {
            float4 b = *(const float4*)&KV[kk][tx * 4];
            float br[4] = {b.x, b.y, b.z, b.w};
#pragma unroll
            for (int i = 0; i < 4; i++) {
                const float a = Ps[ty * 4 + i][kk];
#pragma unroll
                for (int j = 0; j < 4; j++) o[i][j] = fmaf(a, br[j], o[i][j]);
            }
        }
    }

    float inv[4];
#pragma unroll
    for (int i = 0; i < 4; i++) {
#pragma unroll
        for (int off = 1; off < 16; off <<= 1)
            rsum[i] += __shfl_xor_sync(0xffffffff, rsum[i], off);
        inv[i] = 1.0f / rsum[i];
    }

    const int b_ = bh >> 4;
    const int h = bh & 15;
#pragma unroll
    for (int i = 0; i < 4; i++) {
        const int srow = r0 + ty * 4 + i;
        *(float4*)(att + ((size_t)b_ * SS + srow) * DD + h * HDD + tx * 4) =
            make_float4(o[i][0] * inv[i], o[i][1] * inv[i],
                        o[i][2] * inv[i], o[i][3] * inv[i]);
    }

    for (int jt = 0; jt <= rt; jt++) {
#pragma unroll
        for (int i = 0; i < 4; i++) {
            float4* p = (float4*)(Pb + (size_t)(r0 + ty * 4 + i) * SS + jt * 64 + tx * 4);
            float4 t = *p;
            t.x *= inv[i]; t.y *= inv[i]; t.z *= inv[i]; t.w *= inv[i];
            *p = t;
        }
    }
    const float4 z = make_float4(0.f, 0.f, 0.f, 0.f);
    for (int jt = rt + 1; jt < SS / 64; jt++) {
#pragma unroll
        for (int i = 0; i < 4; i++)
            *(float4*)(Pb + (size_t)(r0 + ty * 4 + i) * SS + jt * 64 + tx * 4) = z;
    }
}

// ---------------------------------------------------------------------------
// Launch
// Inputs: query, key, value, mask, Wq, bq, Wk, bk, Wv, bv, Wo, bo
// ---------------------------------------------------------------------------
extern "C" void kernel_launch(void* const* d_in, const int* in_sizes, int n_in,
                              void* d_out, int out_size)
{
    const float* query = (const float*)d_in[0];
    const float* key_  = (const float*)d_in[1];
    const float* value = (const float*)d_in[2];
    // d_in[3] = mask (bool): causal, implied -> unused
    const float* Wq = (const float*)d_in[4];
    const float* bq = (const float*)d_in[5];
    const float* Wk = (const float*)d_in[6];
    const float* bk = (const float*)d_in[7];
    const float* Wv = (const float*)d_in[8];
    const float* bv = (const float*)d_in[9];
    const float* Wo = (const float*)d_in[10];
    const float* bo = (const float*)d_in[11];
    float* out = (float*)d_out;

    float *q_, *k_, *v_, *att_, *Pfb_;
    __nv_bfloat16 *ah_, *al_, *wh_, *wl_;
    cudaGetSymbolAddress((void**)&q_,   g_q);
    cudaGetSymbolAddress((void**)&k_,   g_k);
    cudaGetSymbolAddress((void**)&v_,   g_v);
    cudaGetSymbolAddress((void**)&att_, g_att);
    cudaGetSymbolAddress((void**)&Pfb_, g_P);
    cudaGetSymbolAddress((void**)&ah_,  g_ah);
    cudaGetSymbolAddress((void**)&al_,  g_al);
    cudaGetSymbolAddress((void**)&wh_,  g_wh);
    cudaGetSymbolAddress((void**)&wl_,  g_wl);

    const size_t OUT0 = (size_t)BB * SS * DD;            // 4,194,304
    const size_t PE   = (size_t)BB * HH * SS * SS;       // 134,217,728
    float* P = ((size_t)out_size >= OUT0 + PE) ? (out + OUT0) : Pfb_;

    cudaFuncSetAttribute(gemm_tc, cudaFuncAttributeMaxDynamicSharedMemorySize,
                         GT_SMEM);

    const int NX = MM * DD;   // 4M activation elements
    const int NW = DD * DD;   // 1M weight elements
    dim3 gg(DD / 128, MM / 128);   // (8, 32)

    // Q = query @ Wq^T + bq
    split_kernel<<<2048, 256>>>(query, ah_, al_, NX);
    split_kernel<<<512, 256>>>(Wq, wh_, wl_, NW);
    gemm_tc<<<gg, 256, GT_SMEM>>>(ah_, al_, wh_, wl_, bq, q_, 1);
    // K
    split_kernel<<<2048, 256>>>(key_, ah_, al_, NX);
    split_kernel<<<512, 256>>>(Wk, wh_, wl_, NW);
    gemm_tc<<<gg, 256, GT_SMEM>>>(ah_, al_, wh_, wl_, bk, k_, 1);
    // V
    split_kernel<<<2048, 256>>>(value, ah_, al_, NX);
    split_kernel<<<512, 256>>>(Wv, wh_, wl_, NW);
    gemm_tc<<<gg, 256, GT_SMEM>>>(ah_, al_, wh_, wl_, bv, v_, 1);

    // attention
    dim3 gatt(SS / 64, BB * HH);   // (32, 32)
    attn_fused<<<gatt, 256>>>(q_, k_, v_, P, att_);

    // output projection
    split_kernel<<<2048, 256>>>(att_, ah_, al_, NX);
    split_kernel<<<512, 256>>>(Wo, wh_, wl_, NW);
    gemm_tc<<<gg, 256, GT_SMEM>>>(ah_, al_, wh_, wl_, bo, out, 0);
}

// round 12
// speedup vs baseline: 1.8550x; 1.0829x over previous
#include <cuda_runtime.h>
#include <cuda_bf16.h>
#include <cstdint>

#define BB 2
#define SS 2048
#define DD 1024
#define HH 16
#define HDD 64
#define MM (BB * SS)   // 4096

// ---------------------------------------------------------------------------
// Arch-specific gate: tcgen05 exists only on sm_10xa targets. The harness
// also compiles a generic compute_103 PTX pass, which must see a stub.
// ---------------------------------------------------------------------------
#if defined(__CUDA_ARCH__) && (__CUDA_ARCH__ >= 1000)
#  if defined(__CUDA_ARCH_HAS_FEATURE__)
#    if __CUDA_ARCH_HAS_FEATURE__(SM103_ALL) || __CUDA_ARCH_HAS_FEATURE__(SM100_ALL) || __CUDA_ARCH_HAS_FEATURE__(SM101_ALL)
#      define HAS_TCGEN05 1
#    endif
#  endif
#  if !defined(HAS_TCGEN05) && defined(__CUDA_ARCH_SPECIFIC__)
#    define HAS_TCGEN05 1
#  endif
#  if !defined(HAS_TCGEN05) && defined(__CUDA_ARCH_FEAT_SM103_ALL)
#    define HAS_TCGEN05 1
#  endif
#  if !defined(HAS_TCGEN05) && defined(__CUDA_ARCH_FEAT_SM100_ALL)
#    define HAS_TCGEN05 1
#  endif
#endif

// ---------------------------------------------------------------------------
// Scratch (device globals; allocation is forbidden)
// ---------------------------------------------------------------------------
__device__ float g_q[(size_t)BB * HH * SS * HDD];     // 16 MB  (B,H,S,HD)
__device__ float g_k[(size_t)BB * HH * SS * HDD];     // 16 MB
__device__ float g_v[(size_t)BB * HH * SS * HDD];     // 16 MB
__device__ float g_att[(size_t)BB * SS * DD];         // 16 MB  (B,S,D)
__device__ float g_P[(size_t)BB * HH * SS * SS];      // 512 MB fallback for attn_weights
__device__ __nv_bfloat16 g_ah[(size_t)MM * DD];       // 8 MB  activation hi
__device__ __nv_bfloat16 g_al[(size_t)MM * DD];       // 8 MB  activation lo
__device__ __nv_bfloat16 g_wh[(size_t)DD * DD];       // 2 MB  weight hi
__device__ __nv_bfloat16 g_wl[(size_t)DD * DD];       // 2 MB  weight lo

#ifdef HAS_TCGEN05
// ---------------------------------------------------------------------------
// PTX helpers (tcgen05 / mbarrier) — arch-specific pass only
// ---------------------------------------------------------------------------
__device__ __forceinline__ uint32_t smem_u32(const void* p) {
    uint32_t a;
    asm("{ .reg .u64 t; cvta.to.shared.u64 t, %1; cvt.u32.u64 %0, t; }"
        : "=r"(a) : "l"(p));
    return a;
}
__device__ __forceinline__ uint32_t elect1() {
    uint32_t pred;
    asm volatile(
        "{ .reg .pred p; elect.sync _|p, 0xFFFFFFFF; selp.b32 %0, 1, 0, p; }"
        : "=r"(pred));
    return pred;
}

#define TC_ALLOC(smem_addr, ncols) \
    asm volatile("tcgen05.alloc.cta_group::1.sync.aligned.shared::cta.b32 [%0], %1;" \
                 :: "r"(smem_addr), "r"((uint32_t)(ncols)) : "memory")
#define TC_RELINQ() \
    asm volatile("tcgen05.relinquish_alloc_permit.cta_group::1.sync.aligned;")
#define TC_DEALLOC(tmem, ncols) \
    asm volatile("tcgen05.dealloc.cta_group::1.sync.aligned.b32 %0, %1;" \
                 :: "r"(tmem), "r"((uint32_t)(ncols)))
#define TC_COMMIT(mbar) \
    asm volatile("tcgen05.commit.cta_group::1.mbarrier::arrive::one.shared::cluster.b64 [%0];" \
                 :: "r"(mbar) : "memory")
#define TC_FENCE_AFTER() \
    asm volatile("tcgen05.fence::after_thread_sync;" ::: "memory")
#define TC_WAIT_LD() \
    asm volatile("tcgen05.wait::ld.sync.aligned;" ::: "memory")
#define FENCE_ASYNC_SHARED() \
    asm volatile("fence.proxy.async.shared::cta;" ::: "memory")
#define MBAR_INIT(mbar, cnt) \
    asm volatile("mbarrier.init.shared.b64 [%0], %1;" \
                 :: "r"(mbar), "r"((uint32_t)(cnt)) : "memory")
#define MBAR_INVAL(mbar) \
    asm volatile("mbarrier.inval.shared.b64 [%0];" :: "r"(mbar) : "memory")

#define MBAR_WAIT_PARITY(mbar_a, par) do {                                      \
    uint32_t _m = (mbar_a); uint32_t _p = (par); uint32_t _d;                   \
    asm volatile(                                                               \
        "{\n\t.reg .pred p;\n\t"                                                \
        "mbarrier.try_wait.parity.acquire.cta.shared::cta.b64 p, [%1], %2;\n\t" \
        "selp.b32 %0, 1, 0, p;\n\t}"                                            \
        : "=r"(_d) : "r"(_m), "r"(_p) : "memory");                              \
    if (!_d) {                                                                  \
        asm volatile(                                                           \
            "{\n\t.reg .pred P1;\n\t"                                           \
            "WL_%=:\n\t"                                                        \
            "mbarrier.try_wait.parity.acquire.cta.shared::cta.b64 P1, [%0], %1, 0x989680;\n\t" \
            "@P1 bra.uni WD_%=;\n\t"                                            \
            "bra.uni WL_%=;\n\t"                                                \
            "WD_%=:\n\t}"                                                       \
            :: "r"(_m), "r"(_p) : "memory");                                    \
    }                                                                           \
} while (0)

#define TC_LD_32X32B_X32(r, tmem_addr) \
    asm volatile( \
        "tcgen05.ld.sync.aligned.32x32b.x32.b32 " \
        "{%0, %1, %2, %3, %4, %5, %6, %7, " \
        " %8, %9, %10, %11, %12, %13, %14, %15, " \
        " %16, %17, %18, %19, %20, %21, %22, %23, " \
        " %24, %25, %26, %27, %28, %29, %30, %31}, [%32];" \
        : "=r"((r)[0]),  "=r"((r)[1]),  "=r"((r)[2]),  "=r"((r)[3]), \
          "=r"((r)[4]),  "=r"((r)[5]),  "=r"((r)[6]),  "=r"((r)[7]), \
          "=r"((r)[8]),  "=r"((r)[9]),  "=r"((r)[10]), "=r"((r)[11]), \
          "=r"((r)[12]), "=r"((r)[13]), "=r"((r)[14]), "=r"((r)[15]), \
          "=r"((r)[16]), "=r"((r)[17]), "=r"((r)[18]), "=r"((r)[19]), \
          "=r"((r)[20]), "=r"((r)[21]), "=r"((r)[22]), "=r"((r)[23]), \
          "=r"((r)[24]), "=r"((r)[25]), "=r"((r)[26]), "=r"((r)[27]), \
          "=r"((r)[28]), "=r"((r)[29]), "=r"((r)[30]), "=r"((r)[31]) \
        : "r"(tmem_addr))

// SS-mode cg1 bf16 MMA: D[m,n] += A[m,k]*B[n,k], A/B K-major in smem.
__device__ __forceinline__ void mma_bf16_ss(
    uint32_t d, uint64_t da, uint64_t db, uint32_t idesc, uint32_t en)
{
    asm volatile(
        "{\n\t"
        ".reg .pred p;\n\t"
        "setp.ne.u32 p, %5, 0;\n\t"
        "tcgen05.mma.cta_group::1.kind::f16 [%0], %1, %2, %3, {%4, %4, %4, %4}, p;\n\t"
        "}"
        :: "r"(d), "l"(da), "l"(db), "r"(idesc), "r"(0u), "r"(en)
        : "memory");
}

// SW128 smem descriptor: layout=2(SW128), version=1, SBO=64, LBO=1
static __device__ __forceinline__ uint64_t make_desc(uint32_t addr) {
    const uint64_t base =
        (uint64_t(2) << 61) | (uint64_t(1) << 46) |
        (uint64_t(64) << 32) | (uint64_t(1) << 16);
    return base | ((uint64_t)(addr >> 4) & 0x3FFF);
}

// idesc: f32 acc, bf16 a/b, M=128, N=128
#define GT_IDESC ((1u << 4) | (1u << 7) | (1u << 10) | ((128u / 8) << 17) | ((128u / 16) << 24))
#endif  // HAS_TCGEN05

// ---------------------------------------------------------------------------
// split: x(fp32) -> hi, lo (bf16), x ≈ hi + lo
// ---------------------------------------------------------------------------
__global__ __launch_bounds__(256) void split_kernel(
    const float* __restrict__ x, __nv_bfloat16* __restrict__ hi,
    __nv_bfloat16* __restrict__ lo, int n)
{
    const int stride = gridDim.x * blockDim.x * 4;
    for (int i = (blockIdx.x * blockDim.x + threadIdx.x) * 4; i < n; i += stride) {
        float4 v = *(const float4*)(x + i);
        __nv_bfloat16 h0 = __float2bfloat16(v.x);
        __nv_bfloat16 h1 = __float2bfloat16(v.y);
        __nv_bfloat16 h2 = __float2bfloat16(v.z);
        __nv_bfloat16 h3 = __float2bfloat16(v.w);
        __nv_bfloat162 hp0; hp0.x = h0; hp0.y = h1;
        __nv_bfloat162 hp1; hp1.x = h2; hp1.y = h3;
        *(__nv_bfloat162*)(hi + i)     = hp0;
        *(__nv_bfloat162*)(hi + i + 2) = hp1;
        __nv_bfloat162 lp0, lp1;
        lp0.x = __float2bfloat16(v.x - __bfloat162float(h0));
        lp0.y = __float2bfloat16(v.y - __bfloat162float(h1));
        lp1.x = __float2bfloat16(v.z - __bfloat162float(h2));
        lp1.y = __float2bfloat16(v.w - __bfloat162float(h3));
        *(__nv_bfloat162*)(lo + i)     = lp0;
        *(__nv_bfloat162*)(lo + i + 2) = lp1;
    }
}

// ---------------------------------------------------------------------------
// Tensor-core GEMM (unchanged from passing R11 kernel)
// ---------------------------------------------------------------------------
#define KCH 64
#define NCHUNK (DD / KCH)          // 16
#define TILE_B 16384               // one 128x64 bf16 tile
#define STAGE_B (4 * TILE_B)       // Ah, Al, Bh, Bl
#define GT_SMEM (1024 + 2 * STAGE_B)  // 132096

__global__ __launch_bounds__(256) void gemm_tc(
    const __nv_bfloat16* __restrict__ ah, const __nv_bfloat16* __restrict__ al,
    const __nv_bfloat16* __restrict__ wh, const __nv_bfloat16* __restrict__ wl,
    const float* __restrict__ bias, float* __restrict__ C, int head_layout)
{
#ifdef HAS_TCGEN05
    extern __shared__ __align__(1024) char smem[];
    const uint32_t sb = smem_u32(smem);
    const int tid = threadIdx.x;
    const int wid = tid >> 5;
    const int lid = tid & 31;
    const int bx = blockIdx.x;   // N tile (0..7)
    const int by = blockIdx.y;   // M tile (0..31)

    if (wid == 0) TC_ALLOC(sb, 128);
    __syncthreads();
    uint32_t tmem;
    asm volatile("ld.shared.b32 %0, [%1];" : "=r"(tmem) : "r"(sb));
    if (tid == 0) { MBAR_INIT(sb + 8, 1); MBAR_INIT(sb + 16, 1); }
    if (wid == 0) TC_RELINQ();
    __syncthreads();

    const int row = tid >> 1;
    const int cb0 = (tid & 1) * 8;
    const __nv_bfloat16* pAh = ah + (size_t)(by * 128 + row) * DD + cb0;
    const __nv_bfloat16* pAl = al + (size_t)(by * 128 + row) * DD + cb0;
    const __nv_bfloat16* pBh = wh + (size_t)(bx * 128 + row) * DD + cb0;
    const __nv_bfloat16* pBl = wl + (size_t)(bx * 128 + row) * DD + cb0;
    const uint32_t bo = (uint32_t)(row * 128 + (tid & 1) * 16);

    for (int c = 0; c < NCHUNK; c++) {
        const int kc = c * KCH;
        const int stg = c & 1;
        uint4 va_h[4], va_l[4], vb_h[4], vb_l[4];
#pragma unroll
        for (int i = 0; i < 4; i++) {
            va_h[i] = *(const uint4*)(pAh + kc + 16 * i);
            va_l[i] = *(const uint4*)(pAl + kc + 16 * i);
            vb_h[i] = *(const uint4*)(pBh + kc + 16 * i);
            vb_l[i] = *(const uint4*)(pBl + kc + 16 * i);
        }
        if (c >= 2) {
            const uint32_t ph = (uint32_t)((c >> 1) - 1);
            MBAR_WAIT_PARITY(sb + 8 + 8 * stg, ph & 1);
        }
        char* st = smem + 1024 + stg * STAGE_B;
#pragma unroll
        for (int i = 0; i < 4; i++) {
            uint32_t off = bo + 32 * i;
            uint32_t sw = off ^ ((off >> 3) & 0x70);
            *(uint4*)(st + sw)               = va_h[i];
            *(uint4*)(st + TILE_B + sw)      = va_l[i];
            *(uint4*)(st + 2 * TILE_B + sw)  = vb_h[i];
            *(uint4*)(st + 3 * TILE_B + sw)  = vb_l[i];
        }
        FENCE_ASYNC_SHARED();
        __syncthreads();
        if (wid == 0 && elect1()) {
            const uint32_t sa = sb + 1024 + stg * STAGE_B;
            const uint64_t dAh = make_desc(sa);
            const uint64_t dAl = make_desc(sa + TILE_B);
            const uint64_t dBh = make_desc(sa + 2 * TILE_B);
            const uint64_t dBl = make_desc(sa + 3 * TILE_B);
#pragma unroll
            for (int k = 0; k < 4; k++) {
                mma_bf16_ss(tmem, dAh + k * 2, dBh + k * 2, GT_IDESC,
                            (c == 0 && k == 0) ? 0u : 1u);
                mma_bf16_ss(tmem, dAh + k * 2, dBl + k * 2, GT_IDESC, 1u);
                mma_bf16_ss(tmem, dAl + k * 2, dBh + k * 2, GT_IDESC, 1u);
            }
            TC_COMMIT(sb + 8 + 8 * stg);
        }
    }
    MBAR_WAIT_PARITY(sb + 8,  (uint32_t)((NCHUNK / 2 - 1) & 1));
    MBAR_WAIT_PARITY(sb + 16, (uint32_t)((NCHUNK / 2 - 1) & 1));
    TC_FENCE_AFTER();

    if (wid < 4) {
        const int m = by * 128 + wid * 32 + lid;
        const int b_ = m >> 11;
        const int s = m & (SS - 1);
#pragma unroll
        for (int cb = 0; cb < 4; cb++) {
            uint32_t r[32];
            TC_LD_32X32B_X32(r, tmem + cb * 32);
            TC_WAIT_LD();
#pragma unroll
            for (int j = 0; j < 32; j++) {
                const int n = bx * 128 + cb * 32 + j;
                const float v = __uint_as_float(r[j]) + bias[n];
                if (head_layout) {
                    const int h = n >> 6;
                    const int hd = n & (HDD - 1);
                    C[(((size_t)b_ * HH + h) * SS + s) * HDD + hd] = v;
                } else {
                    C[(size_t)m * DD + n] = v;
                }
            }
        }
    }
    __syncthreads();
    if (tid == 0) { MBAR_INVAL(sb + 8); MBAR_INVAL(sb + 16); }
    __syncthreads();
    if (wid == 0) TC_DEALLOC(tmem, 128);
#endif  // HAS_TCGEN05
}

// ---------------------------------------------------------------------------
// Fused attention v2: 128-row x 64-col tiles, 8x4 accumulators per thread.
// Smem padded (+4 floats/row) for conflict-free transposed stores.
// ---------------------------------------------------------------------------
#define QS_STRIDE 132              // 128 rows + 4 pad
#define KV_STRIDE 68               // 64 + 4 pad
#define PS_STRIDE 68
#define ATT_QS_F  (64 * QS_STRIDE)                  // floats
#define ATT_KV_F  (64 * KV_STRIDE)
#define ATT_PS_F  (128 * PS_STRIDE)
#define ATT_SMEM  ((ATT_QS_F + ATT_KV_F + ATT_PS_F) * 4)   // 86016 bytes

__global__ __launch_bounds__(256) void attn_fused(
    const float* __restrict__ q, const float* __restrict__ k,
    const float* __restrict__ v, float* __restrict__ P,
    float* __restrict__ att)
{
    extern __shared__ __align__(16) float sm[];
    float* Qs = sm;                       // [hd][row] 64 x 132
    float* KVs = sm + ATT_QS_F;           // K: [hd][col] 64x68, then V: [j][d]
    float* Ps = sm + ATT_QS_F + ATT_KV_F; // [row][col] 128 x 68

    const int tid = threadIdx.x;
    const int tx = tid & 15;
    const int ty = tid >> 4;
    const int rt = (int)gridDim.x - 1 - (int)blockIdx.x;  // big tiles first
    const int bh = blockIdx.y;
    const int r0 = rt * 128;

    const float* qb = q + (size_t)bh * SS * HDD;
    const float* kb = k + (size_t)bh * SS * HDD;
    const float* vb = v + (size_t)bh * SS * HDD;
    float* Pb = P + (size_t)bh * SS * SS;

    // load Q tile transposed: Qs[hd][row], 128 rows x 64 hd
    for (int i = tid; i < 128 * 16; i += 256) {
        const int row = i >> 4;
        const int c4 = (i & 15) << 2;
        float4 t = *(const float4*)(qb + (size_t)(r0 + row) * HDD + c4);
        Qs[(c4 + 0) * QS_STRIDE + row] = t.x;
        Qs[(c4 + 1) * QS_STRIDE + row] = t.y;
        Qs[(c4 + 2) * QS_STRIDE + row] = t.z;
        Qs[(c4 + 3) * QS_STRIDE + row] = t.w;
    }

    float o[8][4];
#pragma unroll
    for (int i = 0; i < 8; i++)
#pragma unroll
        for (int j = 0; j < 4; j++) o[i][j] = 0.f;
    float rsum[8];
#pragma unroll
    for (int i = 0; i < 8; i++) rsum[i] = 0.f;

    const int njt = 2 * rt + 2;   // KV col-tiles covering rows r0..r0+127

    for (int jt = 0; jt < njt; jt++) {
        const int j0 = jt * 64;
        __syncthreads();  // protect Qs (1st iter) / KVs,Ps from prev iter
        // load K tile transposed: KVs[hd][col]
        for (int i = tid; i < 64 * 16; i += 256) {
            const int row = i >> 4;
            const int c4 = (i & 15) << 2;
            float4 t = *(const float4*)(kb + (size_t)(j0 + row) * HDD + c4);
            KVs[(c4 + 0) * KV_STRIDE + row] = t.x;
            KVs[(c4 + 1) * KV_STRIDE + row] = t.y;
            KVs[(c4 + 2) * KV_STRIDE + row] = t.z;
            KVs[(c4 + 3) * KV_STRIDE + row] = t.w;
        }
        __syncthreads();

        float s[8][4];
#pragma unroll
        for (int i = 0; i < 8; i++)
#pragma unroll
            for (int j = 0; j < 4; j++) s[i][j] = 0.f;

#pragma unroll 8
        for (int kk = 0; kk < 64; kk++) {
            float4 a0 = *(const float4*)&Qs[kk * QS_STRIDE + ty * 8];
            float4 a1 = *(const float4*)&Qs[kk * QS_STRIDE + ty * 8 + 4];
            float4 b  = *(const float4*)&KVs[kk * KV_STRIDE + tx * 4];
            float ar[8] = {a0.x, a0.y, a0.z, a0.w, a1.x, a1.y, a1.z, a1.w};
            float br[4] = {b.x, b.y, b.z, b.w};
#pragma unroll
            for (int i = 0; i < 8; i++)
#pragma unroll
                for (int j = 0; j < 4; j++) s[i][j] = fmaf(ar[i], br[j], s[i][j]);
        }

        // exp + causal mask; write unnorm P to gmem; stash tile in Ps
#pragma unroll
        for (int i = 0; i < 8; i++) {
            const int lrow = ty * 8 + i;
            const int row = r0 + lrow;
            float pv[4];
#pragma unroll
            for (int j = 0; j < 4; j++) {
                const int col = j0 + tx * 4 + j;
                float p = 0.f;
                if (col <= row) {
                    p = __expf(s[i][j] * 0.125f);
                    rsum[i] += p;
                }
                pv[j] = p;
            }
            float4 pq = make_float4(pv[0], pv[1], pv[2], pv[3]);
            *(float4*)(Pb + (size_t)row * SS + j0 + tx * 4) = pq;
            *(float4*)&Ps[lrow * PS_STRIDE + tx * 4] = pq;
        }
        __syncthreads();  // Ps complete; K reads done

        // load V tile natural: KVs[j][d]
        for (int i = tid; i < 64 * 16; i += 256) {
            const int row = i >> 4;
            const int c4 = (i & 15) << 2;
            *(float4*)&KVs[row * KV_STRIDE + c4] =
                *(const float4*)(vb + (size_t)(j0 + row) * HDD + c4);
        }
        __syncthreads();

        // O += Ps @ V  (kk unrolled by 4, float4 loads both sides)
#pragma unroll 4
        for (int kk = 0; kk < 64; kk += 4) {
            float4 v0 = *(const float4*)&KVs[(kk + 0) * KV_STRIDE + tx * 4];
            float4 v1 = *(const float4*)&KVs[(kk + 1) * KV_STRIDE + tx * 4];
            float4 v2 = *(const float4*)&KVs[(kk + 2) * KV_STRIDE + tx * 4];
            float4 v3 = *(const float4*)&KVs[(kk + 3) * KV_STRIDE + tx * 4];
#pragma unroll
            for (int i = 0; i < 8; i++) {
                float4 pv = *(const float4*)&Ps[(ty * 8 + i) * PS_STRIDE + kk];
                o[i][0] = fmaf(pv.x, v0.x, o[i][0]);
                o[i][1] = fmaf(pv.x, v0.y, o[i][1]);
                o[i][2] = fmaf(pv.x, v0.z, o[i][2]);
                o[i][3] = fmaf(pv.x, v0.w, o[i][3]);
                o[i][0] = fmaf(pv.y, v1.x, o[i][0]);
                o[i][1] = fmaf(pv.y, v1.y, o[i][1]);
                o[i][2] = fmaf(pv.y, v1.z, o[i][2]);
                o[i][3] = fmaf(pv.y, v1.w, o[i][3]);
                o[i][0] = fmaf(pv.z, v2.x, o[i][0]);
                o[i][1] = fmaf(pv.z, v2.y, o[i][1]);
                o[i][2] = fmaf(pv.z, v2.z, o[i][2]);
                o[i][3] = fmaf(pv.z, v2.w, o[i][3]);
                o[i][0] = fmaf(pv.w, v3.x, o[i][0]);
                o[i][1] = fmaf(pv.w, v3.y, o[i][1]);
                o[i][2] = fmaf(pv.w, v3.z, o[i][2]);
                o[i][3] = fmaf(pv.w, v3.w, o[i][3]);
            }
        }
    }

    // row sums: butterfly across tx (lane bits 0..3)
    float inv[8];
#pragma unroll
    for (int i = 0; i < 8; i++) {
#pragma unroll
        for (int off = 1; off < 16; off <<= 1)
            rsum[i] += __shfl_xor_sync(0xffffffff, rsum[i], off);
        inv[i] = 1.0f / rsum[i];
    }

    // write O (normalized) to att (B,S,D)
    const int b_ = bh >> 4;
    const int h = bh & 15;
#pragma unroll
    for (int i = 0; i < 8; i++) {
        const int srow = r0 + ty * 8 + i;
        *(float4*)(att + ((size_t)b_ * SS + srow) * DD + h * HDD + tx * 4) =
            make_float4(o[i][0] * inv[i], o[i][1] * inv[i],
                        o[i][2] * inv[i], o[i][3] * inv[i]);
    }

    // rescale exactly the P elements this thread wrote (per-thread RAW)
    for (int jt = 0; jt < njt; jt++) {
#pragma unroll
        for (int i = 0; i < 8; i++) {
            float4* p = (float4*)(Pb + (size_t)(r0 + ty * 8 + i) * SS + jt * 64 + tx * 4);
            float4 t = *p;
            t.x *= inv[i]; t.y *= inv[i]; t.z *= inv[i]; t.w *= inv[i];
            *p = t;
        }
    }
    // zero-fill fully masked tiles
    const float4 z = make_float4(0.f, 0.f, 0.f, 0.f);
    for (int jt = njt; jt < SS / 64; jt++) {
#pragma unroll
        for (int i = 0; i < 8; i++)
            *(float4*)(Pb + (size_t)(r0 + ty * 8 + i) * SS + jt * 64 + tx * 4) = z;
    }
}

// ---------------------------------------------------------------------------
// Launch
// Inputs: query, key, value, mask, Wq, bq, Wk, bk, Wv, bv, Wo, bo
// ---------------------------------------------------------------------------
extern "C" void kernel_launch(void* const* d_in, const int* in_sizes, int n_in,
                              void* d_out, int out_size)
{
    const float* query = (const float*)d_in[0];
    const float* key_  = (const float*)d_in[1];
    const float* value = (const float*)d_in[2];
    // d_in[3] = mask (bool): causal, implied -> unused
    const float* Wq = (const float*)d_in[4];
    const float* bq = (const float*)d_in[5];
    const float* Wk = (const float*)d_in[6];
    const float* bk = (const float*)d_in[7];
    const float* Wv = (const float*)d_in[8];
    const float* bv = (const float*)d_in[9];
    const float* Wo = (const float*)d_in[10];
    const float* bo = (const float*)d_in[11];
    float* out = (float*)d_out;

    float *q_, *k_, *v_, *att_, *Pfb_;
    __nv_bfloat16 *ah_, *al_, *wh_, *wl_;
    cudaGetSymbolAddress((void**)&q_,   g_q);
    cudaGetSymbolAddress((void**)&k_,   g_k);
    cudaGetSymbolAddress((void**)&v_,   g_v);
    cudaGetSymbolAddress((void**)&att_, g_att);
    cudaGetSymbolAddress((void**)&Pfb_, g_P);
    cudaGetSymbolAddress((void**)&ah_,  g_ah);
    cudaGetSymbolAddress((void**)&al_,  g_al);
    cudaGetSymbolAddress((void**)&wh_,  g_wh);
    cudaGetSymbolAddress((void**)&wl_,  g_wl);

    const size_t OUT0 = (size_t)BB * SS * DD;            // 4,194,304
    const size_t PE   = (size_t)BB * HH * SS * SS;       // 134,217,728
    float* P = ((size_t)out_size >= OUT0 + PE) ? (out + OUT0) : Pfb_;

    cudaFuncSetAttribute(gemm_tc, cudaFuncAttributeMaxDynamicSharedMemorySize,
                         GT_SMEM);
    cudaFuncSetAttribute(attn_fused, cudaFuncAttributeMaxDynamicSharedMemorySize,
                         ATT_SMEM);

    const int NX = MM * DD;   // 4M activation elements
    const int NW = DD * DD;   // 1M weight elements
    dim3 gg(DD / 128, MM / 128);   // (8, 32)

    // Q = query @ Wq^T + bq
    split_kernel<<<2048, 256>>>(query, ah_, al_, NX);
    split_kernel<<<512, 256>>>(Wq, wh_, wl_, NW);
    gemm_tc<<<gg, 256, GT_SMEM>>>(ah_, al_, wh_, wl_, bq, q_, 1);
    // K
    split_kernel<<<2048, 256>>>(key_, ah_, al_, NX);
    split_kernel<<<512, 256>>>(Wk, wh_, wl_, NW);
    gemm_tc<<<gg, 256, GT_SMEM>>>(ah_, al_, wh_, wl_, bk, k_, 1);
    // V
    split_kernel<<<2048, 256>>>(value, ah_, al_, NX);
    split_kernel<<<512, 256>>>(Wv, wh_, wl_, NW);
    gemm_tc<<<gg, 256, GT_SMEM>>>(ah_, al_, wh_, wl_, bv, v_, 1);

    // attention: 128-row tiles
    dim3 gatt(SS / 128, BB * HH);   // (16, 32)
    attn_fused<<<gatt, 256, ATT_SMEM>>>(q_, k_, v_, P, att_);

    // output projection
    split_kernel<<<2048, 256>>>(att_, ah_, al_, NX);
    split_kernel<<<512, 256>>>(Wo, wh_, wl_, NW);
    gemm_tc<<<gg, 256, GT_SMEM>>>(ah_, al_, wh_, wl_, bo, out, 0);
}

// round 14
// speedup vs baseline: 2.2903x; 1.2347x over previous
#include <cuda_runtime.h>
#include <cuda_bf16.h>
#include <cstdint>

#define BB 2
#define SS 2048
#define DD 1024
#define HH 16
#define HDD 64
#define MM (BB * SS)   // 4096

// ---------------------------------------------------------------------------
// Arch-specific gate: tcgen05 exists only on sm_10xa targets.
// ---------------------------------------------------------------------------
#if defined(__CUDA_ARCH__) && (__CUDA_ARCH__ >= 1000)
#  if defined(__CUDA_ARCH_HAS_FEATURE__)
#    if __CUDA_ARCH_HAS_FEATURE__(SM103_ALL) || __CUDA_ARCH_HAS_FEATURE__(SM100_ALL) || __CUDA_ARCH_HAS_FEATURE__(SM101_ALL)
#      define HAS_TCGEN05 1
#    endif
#  endif
#  if !defined(HAS_TCGEN05) && defined(__CUDA_ARCH_SPECIFIC__)
#    define HAS_TCGEN05 1
#  endif
#  if !defined(HAS_TCGEN05) && defined(__CUDA_ARCH_FEAT_SM103_ALL)
#    define HAS_TCGEN05 1
#  endif
#  if !defined(HAS_TCGEN05) && defined(__CUDA_ARCH_FEAT_SM100_ALL)
#    define HAS_TCGEN05 1
#  endif
#endif

// ---------------------------------------------------------------------------
// Scratch (device globals; allocation is forbidden)
// ---------------------------------------------------------------------------
__device__ float g_q[(size_t)BB * HH * SS * HDD];
__device__ float g_k[(size_t)BB * HH * SS * HDD];
__device__ float g_v[(size_t)BB * HH * SS * HDD];
__device__ float g_att[(size_t)BB * SS * DD];
__device__ float g_P[(size_t)BB * HH * SS * SS];
__device__ __nv_bfloat16 g_ah[(size_t)MM * DD];
__device__ __nv_bfloat16 g_al[(size_t)MM * DD];
__device__ __nv_bfloat16 g_wh[(size_t)DD * DD];
__device__ __nv_bfloat16 g_wl[(size_t)DD * DD];

#ifdef HAS_TCGEN05
// ---------------------------------------------------------------------------
// PTX helpers
// ---------------------------------------------------------------------------
__device__ __forceinline__ uint32_t smem_u32(const void* p) {
    uint32_t a;
    asm("{ .reg .u64 t; cvta.to.shared.u64 t, %1; cvt.u32.u64 %0, t; }"
        : "=r"(a) : "l"(p));
    return a;
}
__device__ __forceinline__ uint32_t elect1() {
    uint32_t pred;
    asm volatile(
        "{ .reg .pred p; elect.sync _|p, 0xFFFFFFFF; selp.b32 %0, 1, 0, p; }"
        : "=r"(pred));
    return pred;
}

#define TC_ALLOC(smem_addr, ncols) \
    asm volatile("tcgen05.alloc.cta_group::1.sync.aligned.shared::cta.b32 [%0], %1;" \
                 :: "r"(smem_addr), "r"((uint32_t)(ncols)) : "memory")
#define TC_RELINQ() \
    asm volatile("tcgen05.relinquish_alloc_permit.cta_group::1.sync.aligned;")
#define TC_DEALLOC(tmem, ncols) \
    asm volatile("tcgen05.dealloc.cta_group::1.sync.aligned.b32 %0, %1;" \
                 :: "r"(tmem), "r"((uint32_t)(ncols)))
#define TC_COMMIT(mbar) \
    asm volatile("tcgen05.commit.cta_group::1.mbarrier::arrive::one.shared::cluster.b64 [%0];" \
                 :: "r"(mbar) : "memory")
#define TC_FENCE_AFTER() \
    asm volatile("tcgen05.fence::after_thread_sync;" ::: "memory")
#define TC_FENCE_BEFORE() \
    asm volatile("tcgen05.fence::before_thread_sync;" ::: "memory")
#define TC_WAIT_LD() \
    asm volatile("tcgen05.wait::ld.sync.aligned;" ::: "memory")
#define FENCE_ASYNC_SHARED() \
    asm volatile("fence.proxy.async.shared::cta;" ::: "memory")
#define MBAR_INIT(mbar, cnt) \
    asm volatile("mbarrier.init.shared.b64 [%0], %1;" \
                 :: "r"(mbar), "r"((uint32_t)(cnt)) : "memory")
#define MBAR_INVAL(mbar) \
    asm volatile("mbarrier.inval.shared.b64 [%0];" :: "r"(mbar) : "memory")

#define MBAR_WAIT_PARITY(mbar_a, par) do {                                      \
    uint32_t _m = (mbar_a); uint32_t _p = (par); uint32_t _d;                   \
    asm volatile(                                                               \
        "{\n\t.reg .pred p;\n\t"                                                \
        "mbarrier.try_wait.parity.acquire.cta.shared::cta.b64 p, [%1], %2;\n\t" \
        "selp.b32 %0, 1, 0, p;\n\t}"                                            \
        : "=r"(_d) : "r"(_m), "r"(_p) : "memory");                              \
    if (!_d) {                                                                  \
        asm volatile(                                                           \
            "{\n\t.reg .pred P1;\n\t"                                           \
            "WL_%=:\n\t"                                                        \
            "mbarrier.try_wait.parity.acquire.cta.shared::cta.b64 P1, [%0], %1, 0x989680;\n\t" \
            "@P1 bra.uni WD_%=;\n\t"                                            \
            "bra.uni WL_%=;\n\t"                                                \
            "WD_%=:\n\t}"                                                       \
            :: "r"(_m), "r"(_p) : "memory");                                    \
    }                                                                           \
} while (0)

#define TC_LD_32X32B_X32(r, tmem_addr) \
    asm volatile( \
        "tcgen05.ld.sync.aligned.32x32b.x32.b32 " \
        "{%0, %1, %2, %3, %4, %5, %6, %7, " \
        " %8, %9, %10, %11, %12, %13, %14, %15, " \
        " %16, %17, %18, %19, %20, %21, %22, %23, " \
        " %24, %25, %26, %27, %28, %29, %30, %31}, [%32];" \
        : "=r"((r)[0]),  "=r"((r)[1]),  "=r"((r)[2]),  "=r"((r)[3]), \
          "=r"((r)[4]),  "=r"((r)[5]),  "=r"((r)[6]),  "=r"((r)[7]), \
          "=r"((r)[8]),  "=r"((r)[9]),  "=r"((r)[10]), "=r"((r)[11]), \
          "=r"((r)[12]), "=r"((r)[13]), "=r"((r)[14]), "=r"((r)[15]), \
          "=r"((r)[16]), "=r"((r)[17]), "=r"((r)[18]), "=r"((r)[19]), \
          "=r"((r)[20]), "=r"((r)[21]), "=r"((r)[22]), "=r"((r)[23]), \
          "=r"((r)[24]), "=r"((r)[25]), "=r"((r)[26]), "=r"((r)[27]), \
          "=r"((r)[28]), "=r"((r)[29]), "=r"((r)[30]), "=r"((r)[31]) \
        : "r"(tmem_addr))

__device__ __forceinline__ void mma_bf16_ss(
    uint32_t d, uint64_t da, uint64_t db, uint32_t idesc, uint32_t en)
{
    asm volatile(
        "{\n\t"
        ".reg .pred p;\n\t"
        "setp.ne.u32 p, %5, 0;\n\t"
        "tcgen05.mma.cta_group::1.kind::f16 [%0], %1, %2, %3, {%4, %4, %4, %4}, p;\n\t"
        "}"
        :: "r"(d), "l"(da), "l"(db), "r"(idesc), "r"(0u), "r"(en)
        : "memory");
}

static __device__ __forceinline__ uint64_t make_desc(uint32_t addr) {
    const uint64_t base =
        (uint64_t(2) << 61) | (uint64_t(1) << 46) |
        (uint64_t(64) << 32) | (uint64_t(1) << 16);
    return base | ((uint64_t)(addr >> 4) & 0x3FFF);
}

#define SMZ(off) ((off) ^ (((off) >> 3) & 0x70))

// idesc: f32 acc, bf16 a/b
#define GT_IDESC ((1u << 4) | (1u << 7) | (1u << 10) | ((128u / 8) << 17) | ((128u / 16) << 24))  // M=128,N=128
#define AT_IDESC ((1u << 4) | (1u << 7) | (1u << 10) | ((64u / 8) << 17) | ((128u / 16) << 24))   // M=128,N=64
#endif  // HAS_TCGEN05

// ---------------------------------------------------------------------------
// split: x(fp32) -> hi, lo (bf16)
// ---------------------------------------------------------------------------
__global__ __launch_bounds__(256) void split_kernel(
    const float* __restrict__ x, __nv_bfloat16* __restrict__ hi,
    __nv_bfloat16* __restrict__ lo, int n)
{
    const int stride = gridDim.x * blockDim.x * 4;
    for (int i = (blockIdx.x * blockDim.x + threadIdx.x) * 4; i < n; i += stride) {
        float4 v = *(const float4*)(x + i);
        __nv_bfloat16 h0 = __float2bfloat16(v.x);
        __nv_bfloat16 h1 = __float2bfloat16(v.y);
        __nv_bfloat16 h2 = __float2bfloat16(v.z);
        __nv_bfloat16 h3 = __float2bfloat16(v.w);
        __nv_bfloat162 hp0; hp0.x = h0; hp0.y = h1;
        __nv_bfloat162 hp1; hp1.x = h2; hp1.y = h3;
        *(__nv_bfloat162*)(hi + i)     = hp0;
        *(__nv_bfloat162*)(hi + i + 2) = hp1;
        __nv_bfloat162 lp0, lp1;
        lp0.x = __float2bfloat16(v.x - __bfloat162float(h0));
        lp0.y = __float2bfloat16(v.y - __bfloat162float(h1));
        lp1.x = __float2bfloat16(v.z - __bfloat162float(h2));
        lp1.y = __float2bfloat16(v.w - __bfloat162float(h3));
        *(__nv_bfloat162*)(lo + i)     = lp0;
        *(__nv_bfloat162*)(lo + i + 2) = lp1;
    }
}

// ---------------------------------------------------------------------------
// Tensor-core projection GEMM (unchanged from passing R12 kernel)
// ---------------------------------------------------------------------------
#define KCH 64
#define NCHUNK (DD / KCH)
#define TILE_B 16384
#define STAGE_B (4 * TILE_B)
#define GT_SMEM (1024 + 2 * STAGE_B)

__global__ __launch_bounds__(256) void gemm_tc(
    const __nv_bfloat16* __restrict__ ah, const __nv_bfloat16* __restrict__ al,
    const __nv_bfloat16* __restrict__ wh, const __nv_bfloat16* __restrict__ wl,
    const float* __restrict__ bias, float* __restrict__ C, int head_layout)
{
#ifdef HAS_TCGEN05
    extern __shared__ __align__(1024) char smem[];
    const uint32_t sb = smem_u32(smem);
    const int tid = threadIdx.x;
    const int wid = tid >> 5;
    const int lid = tid & 31;
    const int bx = blockIdx.x;
    const int by = blockIdx.y;

    if (wid == 0) TC_ALLOC(sb, 128);
    __syncthreads();
    uint32_t tmem;
    asm volatile("ld.shared.b32 %0, [%1];" : "=r"(tmem) : "r"(sb));
    if (tid == 0) { MBAR_INIT(sb + 8, 1); MBAR_INIT(sb + 16, 1); }
    if (wid == 0) TC_RELINQ();
    __syncthreads();

    const int row = tid >> 1;
    const int cb0 = (tid & 1) * 8;
    const __nv_bfloat16* pAh = ah + (size_t)(by * 128 + row) * DD + cb0;
    const __nv_bfloat16* pAl = al + (size_t)(by * 128 + row) * DD + cb0;
    const __nv_bfloat16* pBh = wh + (size_t)(bx * 128 + row) * DD + cb0;
    const __nv_bfloat16* pBl = wl + (size_t)(bx * 128 + row) * DD + cb0;
    const uint32_t bo = (uint32_t)(row * 128 + (tid & 1) * 16);

    for (int c = 0; c < NCHUNK; c++) {
        const int kc = c * KCH;
        const int stg = c & 1;
        uint4 va_h[4], va_l[4], vb_h[4], vb_l[4];
#pragma unroll
        for (int i = 0; i < 4; i++) {
            va_h[i] = *(const uint4*)(pAh + kc + 16 * i);
            va_l[i] = *(const uint4*)(pAl + kc + 16 * i);
            vb_h[i] = *(const uint4*)(pBh + kc + 16 * i);
            vb_l[i] = *(const uint4*)(pBl + kc + 16 * i);
        }
        if (c >= 2) {
            const uint32_t ph = (uint32_t)((c >> 1) - 1);
            MBAR_WAIT_PARITY(sb + 8 + 8 * stg, ph & 1);
        }
        char* st = smem + 1024 + stg * STAGE_B;
#pragma unroll
        for (int i = 0; i < 4; i++) {
            uint32_t off = bo + 32 * i;
            uint32_t sw = SMZ(off);
            *(uint4*)(st + sw)               = va_h[i];
            *(uint4*)(st + TILE_B + sw)      = va_l[i];
            *(uint4*)(st + 2 * TILE_B + sw)  = vb_h[i];
            *(uint4*)(st + 3 * TILE_B + sw)  = vb_l[i];
        }
        FENCE_ASYNC_SHARED();
        __syncthreads();
        if (wid == 0 && elect1()) {
            const uint32_t sa = sb + 1024 + stg * STAGE_B;
            const uint64_t dAh = make_desc(sa);
            const uint64_t dAl = make_desc(sa + TILE_B);
            const uint64_t dBh = make_desc(sa + 2 * TILE_B);
            const uint64_t dBl = make_desc(sa + 3 * TILE_B);
#pragma unroll
            for (int k = 0; k < 4; k++) {
                mma_bf16_ss(tmem, dAh + k * 2, dBh + k * 2, GT_IDESC,
                            (c == 0 && k == 0) ? 0u : 1u);
                mma_bf16_ss(tmem, dAh + k * 2, dBl + k * 2, GT_IDESC, 1u);
                mma_bf16_ss(tmem, dAl + k * 2, dBh + k * 2, GT_IDESC, 1u);
            }
            TC_COMMIT(sb + 8 + 8 * stg);
        }
    }
    MBAR_WAIT_PARITY(sb + 8,  (uint32_t)((NCHUNK / 2 - 1) & 1));
    MBAR_WAIT_PARITY(sb + 16, (uint32_t)((NCHUNK / 2 - 1) & 1));
    TC_FENCE_AFTER();

    if (wid < 4) {
        const int m = by * 128 + wid * 32 + lid;
        const int b_ = m >> 11;
        const int s = m & (SS - 1);
#pragma unroll
        for (int cb = 0; cb < 4; cb++) {
            uint32_t r[32];
            TC_LD_32X32B_X32(r, tmem + cb * 32);
            TC_WAIT_LD();
#pragma unroll
            for (int j = 0; j < 32; j++) {
                const int n = bx * 128 + cb * 32 + j;
                const float v = __uint_as_float(r[j]) + bias[n];
                if (head_layout) {
                    const int h = n >> 6;
                    const int hd = n & (HDD - 1);
                    C[(((size_t)b_ * HH + h) * SS + s) * HDD + hd] = v;
                } else {
                    C[(size_t)m * DD + n] = v;
                }
            }
        }
    }
    __syncthreads();
    if (tid == 0) { MBAR_INVAL(sb + 8); MBAR_INVAL(sb + 16); }
    __syncthreads();
    if (wid == 0) TC_DEALLOC(tmem, 128);
#endif
}

// ---------------------------------------------------------------------------
// Tensor-core fused attention.
// Per (bh, 128-row tile): Q split-bf16 resident; per 64-col KV tile:
//  K split K-major, V split TRANSPOSED ([d][j], K-major over j),
//  S=QK^T (12 MMAs) -> TMEM[0..63]; LDTM+exp+causal (thread=row/half),
//  unnorm P fp32 -> gmem, split-bf16 P -> smem; AV (12 MMAs) -> TMEM[64..127].
// mbars: m0 per-tile (QK), m1 1-lag (AV protects K/V/P smem reuse).
// FIX vs R13 draft: K/V tile load now covers all 64 rows (4 prefetch iters).
// ---------------------------------------------------------------------------
#define AQH 1024
#define AQL (AQH + 16384)
#define AKH (AQL + 16384)
#define AKL (AKH + 8192)
#define AVH (AKL + 8192)
#define AVL (AVH + 8192)
#define APH (AVL + 8192)
#define APL (APH + 16384)
#define ARS (APL + 16384)          // 128 x 2 floats
#define AT_SMEM (ARS + 1024)       // 100352

__global__ __launch_bounds__(256) void attn_tc(
    const float* __restrict__ q, const float* __restrict__ k,
    const float* __restrict__ v, float* __restrict__ P,
    float* __restrict__ att)
{
#ifdef HAS_TCGEN05
    extern __shared__ __align__(1024) char smem[];
    const uint32_t sb = smem_u32(smem);
    float* rs = (float*)(smem + ARS);

    const int tid = threadIdx.x;
    const int wid = tid >> 5;
    const int lane = tid & 31;
    const int rt = (int)gridDim.x - 1 - (int)blockIdx.x;
    const int bh = blockIdx.y;
    const int r0 = rt * 128;

    const float* qb = q + (size_t)bh * SS * HDD;
    const float* kb = k + (size_t)bh * SS * HDD;
    const float* vb = v + (size_t)bh * SS * HDD;
    float* Pb = P + (size_t)bh * SS * SS;

    if (wid == 0) TC_ALLOC(sb, 128);
    __syncthreads();
    uint32_t tmem;
    asm volatile("ld.shared.b32 %0, [%1];" : "=r"(tmem) : "r"(sb));
    if (tid == 0) { MBAR_INIT(sb + 8, 1); MBAR_INIT(sb + 16, 1); }
    if (wid == 0) TC_RELINQ();

    // load Q tile [128 rows][64 hd] fp32 -> split bf16 K-major swizzled
    for (int i = tid; i < 128 * 16; i += 256) {
        const int row = i >> 4;
        const int c4 = (i & 15) << 2;
        float4 t = *(const float4*)(qb + (size_t)(r0 + row) * HDD + c4);
        uint32_t off = (uint32_t)(row * 128 + c4 * 2);  // 8B aligned
        uint32_t sw = SMZ(off);
        __nv_bfloat162 h01, h23, l01, l23;
        h01.x = __float2bfloat16(t.x); h01.y = __float2bfloat16(t.y);
        h23.x = __float2bfloat16(t.z); h23.y = __float2bfloat16(t.w);
        l01.x = __float2bfloat16(t.x - __bfloat162float(h01.x));
        l01.y = __float2bfloat16(t.y - __bfloat162float(h01.y));
        l23.x = __float2bfloat16(t.z - __bfloat162float(h23.x));
        l23.y = __float2bfloat16(t.w - __bfloat162float(h23.y));
        *(__nv_bfloat162*)(smem + AQH + sw)     = h01;
        *(__nv_bfloat162*)(smem + AQH + sw + 4) = h23;
        *(__nv_bfloat162*)(smem + AQL + sw)     = l01;
        *(__nv_bfloat162*)(smem + AQL + sw + 4) = l23;
    }
    __syncthreads();

    const int row = (wid & 3) * 32 + lane;   // TMEM lane = row
    const int half = wid >> 2;               // col half (0: 0-31, 1: 32-63)
    const int colbase = half * 32;
    float rsum = 0.f;

    const uint64_t dQh = make_desc(sb + AQH);
    const uint64_t dQl = make_desc(sb + AQL);
    const uint64_t dKh = make_desc(sb + AKH);
    const uint64_t dKl = make_desc(sb + AKL);
    const uint64_t dVh = make_desc(sb + AVH);
    const uint64_t dVl = make_desc(sb + AVL);
    const uint64_t dPh = make_desc(sb + APH);
    const uint64_t dPl = make_desc(sb + APL);

    const int njt = 2 * rt + 2;

    for (int jt = 0; jt < njt; jt++) {
        const int j0 = jt * 64;

        // prefetch K/V tile [64 rows][64 hd]: 1024 float4 items / 256 thr = 4 iters
        float4 tk[4], tv[4];
#pragma unroll
        for (int it = 0; it < 4; it++) {
            const int i = tid + it * 256;
            const int kr = i >> 4;
            const int c4 = (i & 15) << 2;
            tk[it] = *(const float4*)(kb + (size_t)(j0 + kr) * HDD + c4);
            tv[it] = *(const float4*)(vb + (size_t)(j0 + kr) * HDD + c4);
        }
        // wait for AV of tile jt-1 before overwriting K/V/P smem
        if (jt >= 1) MBAR_WAIT_PARITY(sb + 16, (uint32_t)((jt - 1) & 1));
#pragma unroll
        for (int it = 0; it < 4; it++) {
            const int i = tid + it * 256;
            const int kr = i >> 4;
            const int c4 = (i & 15) << 2;
            // K: K-major swizzled
            uint32_t off = (uint32_t)(kr * 128 + c4 * 2);
            uint32_t sw = SMZ(off);
            __nv_bfloat162 h01, h23, l01, l23;
            h01.x = __float2bfloat16(tk[it].x); h01.y = __float2bfloat16(tk[it].y);
            h23.x = __float2bfloat16(tk[it].z); h23.y = __float2bfloat16(tk[it].w);
            l01.x = __float2bfloat16(tk[it].x - __bfloat162float(h01.x));
            l01.y = __float2bfloat16(tk[it].y - __bfloat162float(h01.y));
            l23.x = __float2bfloat16(tk[it].z - __bfloat162float(h23.x));
            l23.y = __float2bfloat16(tk[it].w - __bfloat162float(h23.y));
            *(__nv_bfloat162*)(smem + AKH + sw)     = h01;
            *(__nv_bfloat162*)(smem + AKH + sw + 4) = h23;
            *(__nv_bfloat162*)(smem + AKL + sw)     = l01;
            *(__nv_bfloat162*)(smem + AKL + sw + 4) = l23;
            // V transposed: element (j=kr, d=c4+e) -> row d, col kr
            float ve[4] = {tv[it].x, tv[it].y, tv[it].z, tv[it].w};
#pragma unroll
            for (int e = 0; e < 4; e++) {
                const int d = c4 + e;
                uint32_t o2 = (uint32_t)(d * 128 + kr * 2);
                uint32_t s2 = SMZ(o2);
                __nv_bfloat16 hh = __float2bfloat16(ve[e]);
                *(__nv_bfloat16*)(smem + AVH + s2) = hh;
                *(__nv_bfloat16*)(smem + AVL + s2) =
                    __float2bfloat16(ve[e] - __bfloat162float(hh));
            }
        }
        FENCE_ASYNC_SHARED();
        __syncthreads();

        // QK^T -> S TMEM (cols 0..63)
        if (wid == 0 && elect1()) {
#pragma unroll
            for (int kk = 0; kk < 4; kk++) {
                mma_bf16_ss(tmem, dQh + kk * 2, dKh + kk * 2, AT_IDESC,
                            (kk == 0) ? 0u : 1u);
                mma_bf16_ss(tmem, dQh + kk * 2, dKl + kk * 2, AT_IDESC, 1u);
                mma_bf16_ss(tmem, dQl + kk * 2, dKh + kk * 2, AT_IDESC, 1u);
            }
            TC_COMMIT(sb + 8);
        }
        MBAR_WAIT_PARITY(sb + 8, (uint32_t)(jt & 1));
        TC_FENCE_AFTER();

        // epilogue: thread = (row, half): 32 S cols
        uint32_t sr[32];
        TC_LD_32X32B_X32(sr, tmem + colbase);
        TC_WAIT_LD();

        const int grow = r0 + row;
        float pv[32];
#pragma unroll
        for (int c = 0; c < 32; c++) {
            const int col = j0 + colbase + c;
            float p = 0.f;
            if (col <= grow) {
                p = __expf(__uint_as_float(sr[c]) * 0.125f);
                rsum += p;
            }
            pv[c] = p;
        }
        // unnorm P fp32 -> gmem (per-row, 128B per thread)
        {
            float* pg = Pb + (size_t)grow * SS + j0 + colbase;
#pragma unroll
            for (int c = 0; c < 32; c += 4)
                *(float4*)(pg + c) = make_float4(pv[c], pv[c+1], pv[c+2], pv[c+3]);
        }
        // split-bf16 P -> smem K-major swizzled
#pragma unroll
        for (int c = 0; c < 32; c += 2) {
            uint32_t off = (uint32_t)(row * 128 + (colbase + c) * 2);  // 4B aligned
            uint32_t sw = SMZ(off);
            __nv_bfloat162 hp, lp;
            hp.x = __float2bfloat16(pv[c]);
            hp.y = __float2bfloat16(pv[c + 1]);
            lp.x = __float2bfloat16(pv[c]     - __bfloat162float(hp.x));
            lp.y = __float2bfloat16(pv[c + 1] - __bfloat162float(hp.y));
            *(__nv_bfloat162*)(smem + APH + sw) = hp;
            *(__nv_bfloat162*)(smem + APL + sw) = lp;
        }
        TC_FENCE_BEFORE();
        FENCE_ASYNC_SHARED();
        __syncthreads();

        // AV: O(TMEM cols 64..127) += P @ V^T
        if (wid == 0 && elect1()) {
#pragma unroll
            for (int kk = 0; kk < 4; kk++) {
                mma_bf16_ss(tmem + 64, dPh + kk * 2, dVh + kk * 2, AT_IDESC,
                            (jt == 0 && kk == 0) ? 0u : 1u);
                mma_bf16_ss(tmem + 64, dPh + kk * 2, dVl + kk * 2, AT_IDESC, 1u);
                mma_bf16_ss(tmem + 64, dPl + kk * 2, dVh + kk * 2, AT_IDESC, 1u);
            }
            TC_COMMIT(sb + 16);
        }
    }
    // final AV completion
    MBAR_WAIT_PARITY(sb + 16, (uint32_t)((njt - 1) & 1));
    TC_FENCE_AFTER();

    // combine row sums
    rs[row * 2 + half] = rsum;
    __syncthreads();
    const float inv = 1.0f / (rs[row * 2] + rs[row * 2 + 1]);

    // read O, normalize, write att (B,S,D)
    {
        uint32_t orr[32];
        TC_LD_32X32B_X32(orr, tmem + 64 + colbase);
        TC_WAIT_LD();
        const int b_ = bh >> 4;
        const int h = bh & 15;
        float* ag = att + ((size_t)b_ * SS + (r0 + row)) * DD + h * HDD + colbase;
#pragma unroll
        for (int c = 0; c < 32; c += 4)
            *(float4*)(ag + c) = make_float4(
                __uint_as_float(orr[c])     * inv,
                __uint_as_float(orr[c + 1]) * inv,
                __uint_as_float(orr[c + 2]) * inv,
                __uint_as_float(orr[c + 3]) * inv);
    }
    __syncthreads();
    // publish inv per row for cooperative rescale
    if (half == 0) rs[row] = inv;
    __syncthreads();

    // rescale P (coalesced cooperative) + zero-fill masked tiles
    {
        const int tx = tid & 15;
        const int ty = tid >> 4;
        for (int jt2 = 0; jt2 < njt; jt2++) {
#pragma unroll
            for (int i = 0; i < 8; i++) {
                const int rr = ty * 8 + i;
                float4* p = (float4*)(Pb + (size_t)(r0 + rr) * SS + jt2 * 64 + tx * 4);
                float4 t = *p;
                const float iv = rs[rr];
                t.x *= iv; t.y *= iv; t.z *= iv; t.w *= iv;
                *p = t;
            }
        }
        const float4 z = make_float4(0.f, 0.f, 0.f, 0.f);
        for (int jt2 = njt; jt2 < SS / 64; jt2++) {
#pragma unroll
            for (int i = 0; i < 8; i++)
                *(float4*)(Pb + (size_t)(r0 + ty * 8 + i) * SS + jt2 * 64 + tx * 4) = z;
        }
    }
    __syncthreads();
    if (tid == 0) { MBAR_INVAL(sb + 8); MBAR_INVAL(sb + 16); }
    __syncthreads();
    if (wid == 0) TC_DEALLOC(tmem, 128);
#endif  // HAS_TCGEN05
}

// ---------------------------------------------------------------------------
// Launch
// ---------------------------------------------------------------------------
extern "C" void kernel_launch(void* const* d_in, const int* in_sizes, int n_in,
                              void* d_out, int out_size)
{
    const float* query = (const float*)d_in[0];
    const float* key_  = (const float*)d_in[1];
    const float* value = (const float*)d_in[2];
    const float* Wq = (const float*)d_in[4];
    const float* bq = (const float*)d_in[5];
    const float* Wk = (const float*)d_in[6];
    const float* bk = (const float*)d_in[7];
    const float* Wv = (const float*)d_in[8];
    const float* bv = (const float*)d_in[9];
    const float* Wo = (const float*)d_in[10];
    const float* bo = (const float*)d_in[11];
    float* out = (float*)d_out;

    float *q_, *k_, *v_, *att_, *Pfb_;
    __nv_bfloat16 *ah_, *al_, *wh_, *wl_;
    cudaGetSymbolAddress((void**)&q_,   g_q);
    cudaGetSymbolAddress((void**)&k_,   g_k);
    cudaGetSymbolAddress((void**)&v_,   g_v);
    cudaGetSymbolAddress((void**)&att_, g_att);
    cudaGetSymbolAddress((void**)&Pfb_, g_P);
    cudaGetSymbolAddress((void**)&ah_,  g_ah);
    cudaGetSymbolAddress((void**)&al_,  g_al);
    cudaGetSymbolAddress((void**)&wh_,  g_wh);
    cudaGetSymbolAddress((void**)&wl_,  g_wl);

    const size_t OUT0 = (size_t)BB * SS * DD;
    const size_t PE   = (size_t)BB * HH * SS * SS;
    float* P = ((size_t)out_size >= OUT0 + PE) ? (out + OUT0) : Pfb_;

    cudaFuncSetAttribute(gemm_tc, cudaFuncAttributeMaxDynamicSharedMemorySize,
                         GT_SMEM);
    cudaFuncSetAttribute(attn_tc, cudaFuncAttributeMaxDynamicSharedMemorySize,
                         AT_SMEM);

    const int NX = MM * DD;
    const int NW = DD * DD;
    dim3 gg(DD / 128, MM / 128);

    split_kernel<<<2048, 256>>>(query, ah_, al_, NX);
    split_kernel<<<512, 256>>>(Wq, wh_, wl_, NW);
    gemm_tc<<<gg, 256, GT_SMEM>>>(ah_, al_, wh_, wl_, bq, q_, 1);
    split_kernel<<<2048, 256>>>(key_, ah_, al_, NX);
    split_kernel<<<512, 256>>>(Wk, wh_, wl_, NW);
    gemm_tc<<<gg, 256, GT_SMEM>>>(ah_, al_, wh_, wl_, bk, k_, 1);
    split_kernel<<<2048, 256>>>(value, ah_, al_, NX);
    split_kernel<<<512, 256>>>(Wv, wh_, wl_, NW);
    gemm_tc<<<gg, 256, GT_SMEM>>>(ah_, al_, wh_, wl_, bv, v_, 1);

    dim3 gatt(SS / 128, BB * HH);   // (16, 32)
    attn_tc<<<gatt, 256, AT_SMEM>>>(q_, k_, v_, P, att_);

    split_kernel<<<2048, 256>>>(att_, ah_, al_, NX);
    split_kernel<<<512, 256>>>(Wo, wh_, wl_, NW);
    gemm_tc<<<gg, 256, GT_SMEM>>>(ah_, al_, wh_, wl_, bo, out, 0);
}